// round 5
// baseline (speedup 1.0000x reference)
#include <cuda_runtime.h>
#include <math.h>
#include <stdint.h>

#define BB 4
#define KK 2048
#define NN 4096
#define CIN 61
#define NBK (BB*KK)
#define NPTS (BB*NN)
#define KNBR 32
#define CNTF 262144.0

typedef unsigned long long ull;

// Scratch
__device__ float g_part[(size_t)128 * NBK];     // transposed BN partials [c][bk]
__device__ float g_A[516];
__device__ int   g_selg[(size_t)NBK * KNBR];
__device__ float g_rel[(size_t)NBK * KNBR * 3];
__device__ float g_h1pre[(size_t)NPTS * 128];
__device__ float g_s1pre[(size_t)NPTS * 64];
__device__ float g_epre[(size_t)NPTS * 4];
__device__ float g_sc[64], g_tc[64];
__device__ float g_C1[64], g_Ce[4];
__device__ float g_Wr1s[192], g_A1s[12];

__device__ __forceinline__ ull ffma2(ull a, ull b, ull c) {
    ull d; asm("fma.rn.f32x2 %0, %1, %2, %3;" : "=l"(d) : "l"(a), "l"(b), "l"(c)); return d;
}
__device__ __forceinline__ ull pk2(float lo, float hi) {
    ull d; asm("mov.b64 %0, {%1, %2};" : "=l"(d) : "f"(lo), "f"(hi)); return d;
}
__device__ __forceinline__ void up2(ull a, float& lo, float& hi) {
    asm("mov.b64 {%0, %1}, %2;" : "=f"(lo), "=f"(hi) : "l"(a));
}

// ---------------------------------------------------------------------------
__global__ void k_prep(const float* __restrict__ att_w, const float* __restrict__ att_b,
                       const float* __restrict__ att_q) {
    int t = blockIdx.x * blockDim.x + threadIdx.x;
    if (t < 512) {
        int c = t >> 2, h = t & 3;
        float s = 0.f;
        #pragma unroll 8
        for (int o = 0; o < 64; o++) s += att_w[c * 256 + h * 64 + o] * att_q[h * 64 + o];
        g_A[t] = s;
    }
    if (t < 4) {
        float s = 0.f;
        #pragma unroll 8
        for (int o = 0; o < 64; o++) s += att_b[t * 64 + o] * att_q[t * 64 + o];
        g_A[512 + t] = s;
    }
}

__global__ void __launch_bounds__(128) k_pre_h1(const float* __restrict__ feats,
                                                const float* __restrict__ nxw1) {
    int row = blockIdx.x, t = threadIdx.x;
    __shared__ float f[61];
    if (t < 61) f[t] = feats[(size_t)row * 61 + t];
    __syncthreads();
    float acc = 0.f;
    #pragma unroll
    for (int c = 0; c < 61; c++) acc += f[c] * nxw1[(3 + c) * 128 + t];
    g_h1pre[(size_t)row * 128 + t] = acc;
}

// block exclusive scan (256 threads)
__device__ __forceinline__ uint blk_scan_excl(uint val, volatile uint* ws, uint* tot) {
    __syncthreads();
    int lane = threadIdx.x & 31, w = threadIdx.x >> 5;
    uint inc = val;
    #pragma unroll
    for (int o = 1; o < 32; o <<= 1) {
        uint x = __shfl_up_sync(0xffffffffu, inc, o);
        if (lane >= o) inc += x;
    }
    if (lane == 31) ws[w] = inc;
    __syncthreads();
    if (threadIdx.x == 0) {
        uint run = 0;
        for (int i = 0; i < 8; i++) { uint x = ws[i]; ws[i] = run; run += x; }
        ws[8] = run;
    }
    __syncthreads();
    if (tot) *tot = ws[8];
    return inc - val + ws[w];
}

extern __shared__ char smraw[];

// ---------------------------------------------------------------------------
// kNN via radix-select. dyn smem: d2u[4096] | hist[2048] | cand ushort[4096]
// ---------------------------------------------------------------------------
__global__ void __launch_bounds__(256) k_knn(const float* __restrict__ keys,
                                             const float* __restrict__ points,
                                             const float* __restrict__ feats) {
    uint* smu  = (uint*)smraw;
    uint* d2u  = smu;
    uint* hist = smu + 4096;
    unsigned short* cand = (unsigned short*)(smu + 6144);

    __shared__ int  sel[KNBR];
    __shared__ uint ws[9];
    __shared__ int  sP1, sM1, sP2, sM2;
    __shared__ ull  wmin[8];

    int bk = blockIdx.x, b = bk >> 11, k = bk & 2047, tid = threadIdx.x;

    float kx = keys[(b * KK + k) * 3 + 0];
    float ky = keys[(b * KK + k) * 3 + 1];
    float kz = keys[(b * KK + k) * 3 + 2];
    const float* pb = points + (size_t)b * NN * 3;

    #pragma unroll
    for (int j = 0; j < 8; j++) hist[tid + j * 256] = 0;
    __syncthreads();

    #pragma unroll
    for (int j = 0; j < 16; j++) {
        int p = tid + j * 256;
        float dx = pb[p * 3 + 0] - kx;
        float dy = pb[p * 3 + 1] - ky;
        float dz = pb[p * 3 + 2] - kz;
        uint u = __float_as_uint(dx * dx + dy * dy + dz * dz);
        d2u[p] = u;
        atomicAdd(&hist[u >> 21], 1u);
    }
    __syncthreads();

    // pass 1: find 11-bit pivot bin
    {
        uint cnt8[8], s = 0;
        #pragma unroll
        for (int j = 0; j < 8; j++) { cnt8[j] = hist[tid * 8 + j]; s += cnt8[j]; }
        uint e = blk_scan_excl(s, ws, 0);
        if (e < KNBR && e + s >= KNBR) {
            uint cum = e;
            #pragma unroll
            for (int j = 0; j < 8; j++) {
                if (cum + cnt8[j] >= KNBR) { sP1 = tid * 8 + j; sM1 = (int)cum; break; }
                cum += cnt8[j];
            }
        }
    }
    __syncthreads();
    int P1 = sP1, m1 = sM1;

    // pass 2: 8-bit refine inside bin P1
    hist[tid] = 0;
    __syncthreads();
    #pragma unroll
    for (int j = 0; j < 16; j++) {
        int p = tid + j * 256;
        uint u = d2u[p];
        if ((int)(u >> 21) == P1) atomicAdd(&hist[(u >> 13) & 255], 1u);
    }
    __syncthreads();
    {
        uint v = hist[tid];
        uint e = blk_scan_excl(v, ws, 0);
        int need1 = KNBR - m1;
        if ((int)e < need1 && (int)(e + v) >= need1) { sP2 = tid; sM2 = (int)e; }
    }
    __syncthreads();
    int P2 = sP2, m2 = sM2;

    // compaction: strictly-below -> sel, boundary -> cand
    uint tot = 0;
    {
        uint fb = 0, fe = 0;
        #pragma unroll
        for (int j = 0; j < 16; j++) {
            int p = tid + j * 256;
            uint u = d2u[p];
            int b1 = (int)(u >> 21);
            if (b1 < P1) fb |= (1u << j);
            else if (b1 == P1) {
                int b2 = (int)((u >> 13) & 255);
                if (b2 < P2) fb |= (1u << j);
                else if (b2 == P2) fe |= (1u << j);
            }
        }
        uint packed = ((uint)__popc(fb) << 16) | (uint)__popc(fe);
        uint e = blk_scan_excl(packed, ws, &tot);
        int bB = (int)(e >> 16), bE = (int)(e & 0xFFFF);
        #pragma unroll
        for (int j = 0; j < 16; j++) {
            int p = tid + j * 256;
            if (fb & (1u << j)) sel[bB++] = p;
            if (fe & (1u << j)) cand[bE++] = (unsigned short)p;
        }
    }
    __syncthreads();

    // argmin rounds on boundary candidates
    {
        int m = m1 + m2, need = KNBR - m, cc = (int)(tot & 0xFFFF);
        for (int r = 0; r < need; r++) {
            ull best = ~0ull;
            for (int i = tid; i < cc; i += 256) {
                int p = cand[i];
                ull key = ((ull)d2u[p] << 32) | (uint)p;
                if (key < best) best = key;
            }
            #pragma unroll
            for (int off = 16; off; off >>= 1) {
                ull o = __shfl_down_sync(0xffffffffu, best, off);
                if (o < best) best = o;
            }
            if ((tid & 31) == 0) wmin[tid >> 5] = best;
            __syncthreads();
            if (tid == 0) {
                ull bb = wmin[0];
                #pragma unroll
                for (int w = 1; w < 8; w++) if (wmin[w] < bb) bb = wmin[w];
                int p = (int)(bb & 0xFFFFFFFFull);
                sel[m + r] = p;
                d2u[p] = 0xFFFFFFFFu;
            }
            __syncthreads();
        }
    }

    // gather comb (reuse d2u region as float cs[2048])
    float* cs = (float*)smu;
    const float* fb2 = feats + (size_t)b * NN * CIN;
    __syncthreads();
    #pragma unroll
    for (int j = 0; j < 8; j++) {
        int e = tid + j * 256;
        int n = e >> 6, c = e & 63;
        int p = sel[n];
        float v;
        if (c < 3) {
            float kc = (c == 0) ? kx : ((c == 1) ? ky : kz);
            v = pb[p * 3 + c] - kc;
        } else v = fb2[p * CIN + (c - 3)];
        cs[e] = v;
    }
    __syncthreads();

    if (tid < 64) {
        float s = 0.f, ss = 0.f;
        #pragma unroll
        for (int n = 0; n < KNBR; n++) { float v = cs[n * 64 + tid]; s += v; ss += v * v; }
        g_part[(size_t)tid * NBK + bk]        = s;
        g_part[(size_t)(64 + tid) * NBK + bk] = ss;
    }
    if (tid < 32) g_selg[(size_t)bk * 32 + tid] = b * NN + sel[tid];
    if (tid < 96) g_rel[(size_t)bk * 96 + tid] = cs[(tid / 3) * 64 + (tid % 3)];
}

// ---------------------------------------------------------------------------
__global__ void __launch_bounds__(256) k_stats(const float* __restrict__ gamma,
                                               const float* __restrict__ beta) {
    int c = blockIdx.x, t = threadIdx.x;
    double s = 0.0, ss = 0.0;
    const float* ps  = g_part + (size_t)c * NBK;
    const float* pss = g_part + (size_t)(64 + c) * NBK;
    for (int i = t; i < NBK; i += 256) { s += (double)ps[i]; ss += (double)pss[i]; }
    __shared__ double rs[256], rss[256];
    rs[t] = s; rss[t] = ss;
    __syncthreads();
    for (int o = 128; o; o >>= 1) {
        if (t < o) { rs[t] += rs[t + o]; rss[t] += rss[t + o]; }
        __syncthreads();
    }
    if (t == 0) {
        double mean = rs[0] / CNTF;
        double var  = rss[0] / CNTF - mean * mean;
        float sc = (float)((1.0 / sqrt(var + 1e-5)) * (double)gamma[c]);
        g_sc[c] = sc;
        g_tc[c] = beta[c] - (float)mean * sc;
    }
}

__global__ void k_const(const float* __restrict__ sxw1, const float* __restrict__ sxb1) {
    int t = threadIdx.x;
    if (t < 64) {
        float s = sxb1[t];
        #pragma unroll 8
        for (int c = 0; c < 64; c++) s += g_tc[c] * sxw1[c * 64 + t];
        g_C1[t] = s;
    }
    if (t < 4) {
        float s = g_A[512 + t];
        #pragma unroll 8
        for (int c = 0; c < 64; c++) s += g_tc[c] * g_A[c * 4 + t];
        g_Ce[t] = s;
    }
    if (t >= 64) {
        int i = t - 64, c = i >> 6, o = i & 63;
        g_Wr1s[i] = g_sc[c] * sxw1[c * 64 + o];
    }
    if (t < 12) g_A1s[t] = g_sc[t >> 2] * g_A[(t >> 2) * 4 + (t & 3)];
}

__global__ void __launch_bounds__(64) k_pre_s1e(const float* __restrict__ feats,
                                                const float* __restrict__ sxw1) {
    int row = blockIdx.x, t = threadIdx.x;
    __shared__ float sf[61];
    if (t < 61) sf[t] = feats[(size_t)row * 61 + t] * g_sc[3 + t];
    __syncthreads();
    float acc = 0.f;
    #pragma unroll
    for (int c = 0; c < 61; c++) acc += sf[c] * sxw1[(3 + c) * 64 + t];
    g_s1pre[(size_t)row * 64 + t] = acc;
    if (t < 4) {
        float s = 0.f;
        #pragma unroll
        for (int c = 0; c < 61; c++) s += sf[c] * g_A[(3 + c) * 4 + t];
        g_epre[(size_t)row * 4 + t] = s;
    }
}

// ---------------------------------------------------------------------------
// pack-over-o GEMM: X smem [64][CI] n-major, W global [CI][CO], Y smem [64][CO]
// 128 threads. OB o's and 64*OB*? ... NB = 64 / (128/(CO/OB)) n per thread.
// ---------------------------------------------------------------------------
template<int CI, int CO, int OB>
__device__ __forceinline__ void gemm_po(const float* __restrict__ X,
                                        const float* __restrict__ W,
                                        const float* __restrict__ Bv,
                                        float* __restrict__ Y, int t, bool relu) {
    constexpr int OP  = OB / 2;
    constexpr int NOG = CO / OB;        // 16
    constexpr int NB  = 64 / (128 / NOG);  // 8
    int og = t % NOG, ng = t / NOG;
    int o0 = og * OB, n0 = ng * NB;
    ull acc[NB][OP];
    #pragma unroll
    for (int i = 0; i < NB; i++)
        #pragma unroll
        for (int p = 0; p < OP; p++) acc[i][p] = 0ull;

    for (int c = 0; c < CI; c += 4) {
        ull w[4][OP];
        #pragma unroll
        for (int j = 0; j < 4; j++)
            #pragma unroll
            for (int p = 0; p < OP; p += 2) {
                ulonglong2 wv = *(const ulonglong2*)(W + (c + j) * CO + o0 + p * 2);
                w[j][p] = wv.x; w[j][p + 1] = wv.y;
            }
        #pragma unroll
        for (int i = 0; i < NB; i++) {
            float4 x4 = *(const float4*)(X + (n0 + i) * CI + c);
            ull xs;
            xs = pk2(x4.x, x4.x);
            #pragma unroll
            for (int p = 0; p < OP; p++) acc[i][p] = ffma2(xs, w[0][p], acc[i][p]);
            xs = pk2(x4.y, x4.y);
            #pragma unroll
            for (int p = 0; p < OP; p++) acc[i][p] = ffma2(xs, w[1][p], acc[i][p]);
            xs = pk2(x4.z, x4.z);
            #pragma unroll
            for (int p = 0; p < OP; p++) acc[i][p] = ffma2(xs, w[2][p], acc[i][p]);
            xs = pk2(x4.w, x4.w);
            #pragma unroll
            for (int p = 0; p < OP; p++) acc[i][p] = ffma2(xs, w[3][p], acc[i][p]);
        }
    }
    #pragma unroll
    for (int p = 0; p < OP; p++) {
        float b0 = Bv[o0 + p * 2], b1 = Bv[o0 + p * 2 + 1];
        #pragma unroll
        for (int i = 0; i < NB; i++) {
            float lo, hi; up2(acc[i][p], lo, hi);
            lo += b0; hi += b1;
            if (relu) { lo = fmaxf(lo, 0.f); hi = fmaxf(hi, 0.f); }
            Y[(n0 + i) * CO + o0 + p * 2]     = lo;
            Y[(n0 + i) * CO + o0 + p * 2 + 1] = hi;
        }
    }
}

// ---------------------------------------------------------------------------
// Fused pipeline, 2 queries/block, 128 threads, 96KB dyn smem.
// layout (floats): h1 [0,8192) | h2 [8192,16384) | lat [16384,20480) | s1 [20480,24576)
// s2 reuses h1, s3 reuses h2.
// ---------------------------------------------------------------------------
__global__ void __launch_bounds__(128) k_main(
    const float* __restrict__ nxw1, const float* __restrict__ nxb1,
    const float* __restrict__ nxw2, const float* __restrict__ nxb2,
    const float* __restrict__ nxw3, const float* __restrict__ nxb3,
    const float* __restrict__ sxw2, const float* __restrict__ sxb2,
    const float* __restrict__ sxw3, const float* __restrict__ sxb3,
    float* __restrict__ out) {
    float* sm = (float*)smraw;
    float* h1  = sm;
    float* h2  = sm + 8192;
    float* lat = sm + 16384;
    float* s1  = sm + 20480;
    float* s2  = sm;            // reuse h1
    float* s3  = sm + 8192;     // reuse h2
    __shared__ float rel_s[192];
    __shared__ int   sel_s[64];
    __shared__ float setf[128];
    __shared__ float gh[8];
    __shared__ float ebuf[256];
    __shared__ float wbuf[256];

    int blk = blockIdx.x, t = threadIdx.x;
    int bk0 = blk * 2;

    if (t < 64) sel_s[t] = g_selg[(size_t)(bk0 + (t >> 5)) * 32 + (t & 31)];
    if (t < 96)  rel_s[t]      = g_rel[(size_t)bk0 * 96 + t];
    else if (t < 128) { /* nothing */ }
    for (int i = t; i < 96; i += 128) {}  // noop
    if (t < 96) rel_s[96 + t] = g_rel[(size_t)(bk0 + 1) * 96 + t];
    __syncthreads();

    // Stage A: h1[n][c] = relu(h1pre + rel.w + b), c = t
    {
        int c = t;
        float wr0 = nxw1[c], wr1 = nxw1[128 + c], wr2 = nxw1[256 + c], bj = nxb1[c];
        #pragma unroll 4
        for (int n = 0; n < 64; n++) {
            int q = n >> 5, nn = n & 31;
            float v = g_h1pre[(size_t)sel_s[n] * 128 + c] + bj
                    + rel_s[q * 96 + nn * 3]     * wr0
                    + rel_s[q * 96 + nn * 3 + 1] * wr1
                    + rel_s[q * 96 + nn * 3 + 2] * wr2;
            h1[n * 128 + c] = fmaxf(v, 0.f);
        }
    }
    __syncthreads();

    gemm_po<128, 128, 8>(h1, nxw2, nxb2, h2, t, true);    // Stage B
    __syncthreads();
    gemm_po<128, 64, 4>(h2, nxw3, nxb3, lat, t, false);   // Stage C
    __syncthreads();

    // Stage D: s1[n][o]
    {
        int o = t & 63, half = t >> 6;
        float w0 = g_Wr1s[o], w1 = g_Wr1s[64 + o], w2 = g_Wr1s[128 + o], c1 = g_C1[o];
        #pragma unroll 4
        for (int i = 0; i < 32; i++) {
            int n = half * 32 + i;
            int q = n >> 5, nn = n & 31;
            float v = g_s1pre[(size_t)sel_s[n] * 64 + o] + c1
                    + rel_s[q * 96 + nn * 3]     * w0
                    + rel_s[q * 96 + nn * 3 + 1] * w1
                    + rel_s[q * 96 + nn * 3 + 2] * w2;
            s1[n * 64 + o] = fmaxf(v, 0.f);
        }
    }
    __syncthreads();

    gemm_po<64, 64, 4>(s1, sxw2, sxb2, s2, t, true);      // Stage E
    __syncthreads();
    gemm_po<64, 64, 4>(s2, sxw3, sxb3, s3, t, false);     // Stage F
    __syncthreads();

    // setf[q][c]
    {
        int q = t >> 6, c = t & 63;
        float s = 0.f;
        #pragma unroll
        for (int n = 0; n < 32; n++) s += s3[(q * 32 + n) * 64 + c];
        setf[q * 64 + c] = s;
    }
    __syncthreads();
    if (t < 8) {
        int q = t >> 2, h = t & 3;
        float s = g_Ce[h];
        #pragma unroll 8
        for (int c = 0; c < 64; c++) s += setf[q * 64 + c] * g_A[(64 + c) * 4 + h];
        gh[t] = s;
    }
    __syncthreads();

    // ebuf
    #pragma unroll
    for (int r = 0; r < 2; r++) {
        int idx = r * 128 + t;
        int q = idx >> 7, i = idx & 127, n = i >> 2, h = i & 3;
        int gn = q * 32 + n;
        ebuf[idx] = gh[q * 4 + h] + g_epre[(size_t)sel_s[gn] * 4 + h]
                  + rel_s[q * 96 + n * 3]     * g_A1s[h]
                  + rel_s[q * 96 + n * 3 + 1] * g_A1s[4 + h]
                  + rel_s[q * 96 + n * 3 + 2] * g_A1s[8 + h];
    }
    __syncthreads();

    if (t < 8) {
        int q = t >> 2, h = t & 3;
        float m = -INFINITY;
        #pragma unroll
        for (int n = 0; n < 32; n++) m = fmaxf(m, ebuf[q * 128 + n * 4 + h]);
        float s = 0.f;
        #pragma unroll
        for (int n = 0; n < 32; n++) {
            float ex = expf(ebuf[q * 128 + n * 4 + h] - m);
            wbuf[q * 128 + n * 4 + h] = ex;
            s += ex;
        }
        float inv = 1.f / s;
        #pragma unroll
        for (int n = 0; n < 32; n++) wbuf[q * 128 + n * 4 + h] *= inv;
    }
    __syncthreads();

    #pragma unroll
    for (int r = 0; r < 4; r++) {
        int idx = r * 128 + t;
        int q = idx >> 8, i = idx & 255, o = i >> 2, h = i & 3;
        float s = 0.f;
        #pragma unroll
        for (int n = 0; n < 32; n++)
            s += lat[(q * 32 + n) * 64 + o] * wbuf[q * 128 + n * 4 + h];
        out[(size_t)(bk0 + q) * 256 + i] = s;
    }
}

// ---------------------------------------------------------------------------
extern "C" void kernel_launch(void* const* d_in, const int* in_sizes, int n_in,
                              void* d_out, int out_size) {
    (void)in_sizes; (void)n_in; (void)out_size;
    const float* keys  = (const float*)d_in[0];
    const float* points= (const float*)d_in[1];
    const float* feats = (const float*)d_in[2];
    const float* nxw1  = (const float*)d_in[3];
    const float* nxb1  = (const float*)d_in[4];
    const float* nxw2  = (const float*)d_in[5];
    const float* nxb2  = (const float*)d_in[6];
    const float* nxw3  = (const float*)d_in[7];
    const float* nxb3  = (const float*)d_in[8];
    const float* sxw1  = (const float*)d_in[9];
    const float* sxb1  = (const float*)d_in[10];
    const float* sxw2  = (const float*)d_in[11];
    const float* sxb2  = (const float*)d_in[12];
    const float* sxw3  = (const float*)d_in[13];
    const float* sxb3  = (const float*)d_in[14];
    const float* attw  = (const float*)d_in[15];
    const float* attb  = (const float*)d_in[16];
    const float* attq  = (const float*)d_in[17];
    const float* gamma = (const float*)d_in[18];
    const float* beta  = (const float*)d_in[19];
    float* out = (float*)d_out;

    static int inited = 0;
    if (!inited) {
        cudaFuncSetAttribute(k_main, cudaFuncAttributeMaxDynamicSharedMemorySize, 98304);
        cudaFuncSetAttribute(k_knn,  cudaFuncAttributeMaxDynamicSharedMemorySize, 32768);
        inited = 1;
    }

    k_prep<<<2, 256>>>(attw, attb, attq);
    k_pre_h1<<<NPTS, 128>>>(feats, nxw1);
    k_knn<<<NBK, 256, 32768>>>(keys, points, feats);
    k_stats<<<64, 256>>>(gamma, beta);
    k_const<<<1, 256>>>(sxw1, sxb1);
    k_pre_s1e<<<NPTS, 64>>>(feats, sxw1);
    k_main<<<NBK / 2, 128, 98304>>>(nxw1, nxb1, nxw2, nxb2, nxw3, nxb3,
                                    sxw2, sxb2, sxw3, sxb3, out);
}

// round 6
// speedup vs baseline: 1.3227x; 1.3227x over previous
#include <cuda_runtime.h>
#include <math.h>
#include <stdint.h>

#define BB 4
#define KK 2048
#define NN 4096
#define CIN 61
#define NBK (BB*KK)
#define NPTS (BB*NN)
#define KNBR 32
#define CNTF 262144.0

typedef unsigned long long ull;

// Scratch (static device globals — allocation-free)
__device__ float g_part[(size_t)128 * NBK];     // transposed BN partials [c][bk]
__device__ float g_A[516];
__device__ int   g_selg[(size_t)NBK * KNBR];
__device__ float g_rel[(size_t)NBK * KNBR * 3];
__device__ float g_h1pre[(size_t)NPTS * 128];
__device__ float g_s1pre[(size_t)NPTS * 64];
__device__ float g_epre[(size_t)NPTS * 4];
__device__ float g_sc[64], g_tc[64];
__device__ float g_C1[64], g_Ce[4];
__device__ float g_Wr1s[192], g_A1s[12];

__device__ __forceinline__ ull ffma2(ull a, ull b, ull c) {
    ull d; asm("fma.rn.f32x2 %0, %1, %2, %3;" : "=l"(d) : "l"(a), "l"(b), "l"(c)); return d;
}
__device__ __forceinline__ ull pk2(float lo, float hi) {
    ull d; asm("mov.b64 %0, {%1, %2};" : "=l"(d) : "f"(lo), "f"(hi)); return d;
}
__device__ __forceinline__ float hsum2(ull a) {
    float lo, hi;
    asm("mov.b64 {%0, %1}, %2;" : "=f"(lo), "=f"(hi) : "l"(a));
    return lo + hi;
}

// ---------------------------------------------------------------------------
__global__ void k_prep(const float* __restrict__ att_w, const float* __restrict__ att_b,
                       const float* __restrict__ att_q) {
    int t = blockIdx.x * blockDim.x + threadIdx.x;
    if (t < 512) {
        int c = t >> 2, h = t & 3;
        float s = 0.f;
        #pragma unroll 8
        for (int o = 0; o < 64; o++) s += att_w[c * 256 + h * 64 + o] * att_q[h * 64 + o];
        g_A[t] = s;
    }
    if (t < 4) {
        float s = 0.f;
        #pragma unroll 8
        for (int o = 0; o < 64; o++) s += att_b[t * 64 + o] * att_q[t * 64 + o];
        g_A[512 + t] = s;
    }
}

__global__ void __launch_bounds__(128) k_pre_h1(const float* __restrict__ feats,
                                                const float* __restrict__ nxw1) {
    int row = blockIdx.x, t = threadIdx.x;
    __shared__ float f[61];
    if (t < 61) f[t] = feats[(size_t)row * 61 + t];
    __syncthreads();
    float acc = 0.f;
    #pragma unroll
    for (int c = 0; c < 61; c++) acc += f[c] * nxw1[(3 + c) * 128 + t];
    g_h1pre[(size_t)row * 128 + t] = acc;
}

// block exclusive scan (256 threads)
__device__ __forceinline__ uint blk_scan_excl(uint val, volatile uint* ws, uint* tot) {
    __syncthreads();
    int lane = threadIdx.x & 31, w = threadIdx.x >> 5;
    uint inc = val;
    #pragma unroll
    for (int o = 1; o < 32; o <<= 1) {
        uint x = __shfl_up_sync(0xffffffffu, inc, o);
        if (lane >= o) inc += x;
    }
    if (lane == 31) ws[w] = inc;
    __syncthreads();
    if (threadIdx.x == 0) {
        uint run = 0;
        for (int i = 0; i < 8; i++) { uint x = ws[i]; ws[i] = run; run += x; }
        ws[8] = run;
    }
    __syncthreads();
    if (tot) *tot = ws[8];
    return inc - val + ws[w];
}

extern __shared__ char smraw[];

// ---------------------------------------------------------------------------
// kNN via radix-select. dyn smem 32KB: d2u[4096] | hist[2048] | cand ushort[4096]
// ---------------------------------------------------------------------------
__global__ void __launch_bounds__(256) k_knn(const float* __restrict__ keys,
                                             const float* __restrict__ points,
                                             const float* __restrict__ feats) {
    uint* smu  = (uint*)smraw;
    uint* d2u  = smu;
    uint* hist = smu + 4096;
    unsigned short* cand = (unsigned short*)(smu + 6144);

    __shared__ int  sel[KNBR];
    __shared__ uint ws[9];
    __shared__ int  sP1, sM1, sP2, sM2;
    __shared__ ull  wmin[8];

    int bk = blockIdx.x, b = bk >> 11, k = bk & 2047, tid = threadIdx.x;

    float kx = keys[(b * KK + k) * 3 + 0];
    float ky = keys[(b * KK + k) * 3 + 1];
    float kz = keys[(b * KK + k) * 3 + 2];
    const float* pb = points + (size_t)b * NN * 3;

    #pragma unroll
    for (int j = 0; j < 8; j++) hist[tid + j * 256] = 0;
    __syncthreads();

    #pragma unroll
    for (int j = 0; j < 16; j++) {
        int p = tid + j * 256;
        float dx = pb[p * 3 + 0] - kx;
        float dy = pb[p * 3 + 1] - ky;
        float dz = pb[p * 3 + 2] - kz;
        uint u = __float_as_uint(dx * dx + dy * dy + dz * dz);
        d2u[p] = u;
        atomicAdd(&hist[u >> 21], 1u);
    }
    __syncthreads();

    // pass 1: find 11-bit pivot bin
    {
        uint cnt8[8], s = 0;
        #pragma unroll
        for (int j = 0; j < 8; j++) { cnt8[j] = hist[tid * 8 + j]; s += cnt8[j]; }
        uint e = blk_scan_excl(s, ws, 0);
        if (e < KNBR && e + s >= KNBR) {
            uint cum = e;
            #pragma unroll
            for (int j = 0; j < 8; j++) {
                if (cum + cnt8[j] >= KNBR) { sP1 = tid * 8 + j; sM1 = (int)cum; break; }
                cum += cnt8[j];
            }
        }
    }
    __syncthreads();
    int P1 = sP1, m1 = sM1;

    // pass 2: 8-bit refine inside bin P1
    hist[tid] = 0;
    __syncthreads();
    #pragma unroll
    for (int j = 0; j < 16; j++) {
        int p = tid + j * 256;
        uint u = d2u[p];
        if ((int)(u >> 21) == P1) atomicAdd(&hist[(u >> 13) & 255], 1u);
    }
    __syncthreads();
    {
        uint v = hist[tid];
        uint e = blk_scan_excl(v, ws, 0);
        int need1 = KNBR - m1;
        if ((int)e < need1 && (int)(e + v) >= need1) { sP2 = tid; sM2 = (int)e; }
    }
    __syncthreads();
    int P2 = sP2, m2 = sM2;

    // compaction: strictly-below -> sel, boundary -> cand
    uint tot = 0;
    {
        uint fb = 0, fe = 0;
        #pragma unroll
        for (int j = 0; j < 16; j++) {
            int p = tid + j * 256;
            uint u = d2u[p];
            int b1 = (int)(u >> 21);
            if (b1 < P1) fb |= (1u << j);
            else if (b1 == P1) {
                int b2 = (int)((u >> 13) & 255);
                if (b2 < P2) fb |= (1u << j);
                else if (b2 == P2) fe |= (1u << j);
            }
        }
        uint packed = ((uint)__popc(fb) << 16) | (uint)__popc(fe);
        uint e = blk_scan_excl(packed, ws, &tot);
        int bB = (int)(e >> 16), bE = (int)(e & 0xFFFF);
        #pragma unroll
        for (int j = 0; j < 16; j++) {
            int p = tid + j * 256;
            if (fb & (1u << j)) sel[bB++] = p;
            if (fe & (1u << j)) cand[bE++] = (unsigned short)p;
        }
    }
    __syncthreads();

    // argmin rounds on boundary candidates (deterministic tie-break: lowest idx)
    {
        int m = m1 + m2, need = KNBR - m, cc = (int)(tot & 0xFFFF);
        for (int r = 0; r < need; r++) {
            ull best = ~0ull;
            for (int i = tid; i < cc; i += 256) {
                int p = cand[i];
                ull key = ((ull)d2u[p] << 32) | (uint)p;
                if (key < best) best = key;
            }
            #pragma unroll
            for (int off = 16; off; off >>= 1) {
                ull o = __shfl_down_sync(0xffffffffu, best, off);
                if (o < best) best = o;
            }
            if ((tid & 31) == 0) wmin[tid >> 5] = best;
            __syncthreads();
            if (tid == 0) {
                ull bb = wmin[0];
                #pragma unroll
                for (int w = 1; w < 8; w++) if (wmin[w] < bb) bb = wmin[w];
                int p = (int)(bb & 0xFFFFFFFFull);
                sel[m + r] = p;
                d2u[p] = 0xFFFFFFFFu;
            }
            __syncthreads();
        }
    }

    // gather comb (reuse d2u region as float cs[2048])
    float* cs = (float*)smu;
    const float* fb2 = feats + (size_t)b * NN * CIN;
    __syncthreads();
    #pragma unroll
    for (int j = 0; j < 8; j++) {
        int e = tid + j * 256;
        int n = e >> 6, c = e & 63;
        int p = sel[n];
        float v;
        if (c < 3) {
            float kc = (c == 0) ? kx : ((c == 1) ? ky : kz);
            v = pb[p * 3 + c] - kc;
        } else v = fb2[p * CIN + (c - 3)];
        cs[e] = v;
    }
    __syncthreads();

    if (tid < 64) {
        float s = 0.f, ss = 0.f;
        #pragma unroll
        for (int n = 0; n < KNBR; n++) { float v = cs[n * 64 + tid]; s += v; ss += v * v; }
        g_part[(size_t)tid * NBK + bk]        = s;
        g_part[(size_t)(64 + tid) * NBK + bk] = ss;
    }
    if (tid < 32) g_selg[(size_t)bk * 32 + tid] = b * NN + sel[tid];
    if (tid < 96) g_rel[(size_t)bk * 96 + tid] = cs[(tid / 3) * 64 + (tid % 3)];
}

// ---------------------------------------------------------------------------
__global__ void __launch_bounds__(256) k_stats(const float* __restrict__ gamma,
                                               const float* __restrict__ beta) {
    int c = blockIdx.x, t = threadIdx.x;
    double s = 0.0, ss = 0.0;
    const float* ps  = g_part + (size_t)c * NBK;
    const float* pss = g_part + (size_t)(64 + c) * NBK;
    for (int i = t; i < NBK; i += 256) { s += (double)ps[i]; ss += (double)pss[i]; }
    __shared__ double rs[256], rss[256];
    rs[t] = s; rss[t] = ss;
    __syncthreads();
    for (int o = 128; o; o >>= 1) {
        if (t < o) { rs[t] += rs[t + o]; rss[t] += rss[t + o]; }
        __syncthreads();
    }
    if (t == 0) {
        double mean = rs[0] / CNTF;
        double var  = rss[0] / CNTF - mean * mean;
        float sc = (float)((1.0 / sqrt(var + 1e-5)) * (double)gamma[c]);
        g_sc[c] = sc;
        g_tc[c] = beta[c] - (float)mean * sc;
    }
}

__global__ void k_const(const float* __restrict__ sxw1, const float* __restrict__ sxb1) {
    int t = threadIdx.x;
    if (t < 64) {
        float s = sxb1[t];
        #pragma unroll 8
        for (int c = 0; c < 64; c++) s += g_tc[c] * sxw1[c * 64 + t];
        g_C1[t] = s;
    }
    if (t < 4) {
        float s = g_A[512 + t];
        #pragma unroll 8
        for (int c = 0; c < 64; c++) s += g_tc[c] * g_A[c * 4 + t];
        g_Ce[t] = s;
    }
    if (t >= 64) {
        int i = t - 64, c = i >> 6, o = i & 63;
        g_Wr1s[i] = g_sc[c] * sxw1[c * 64 + o];
    }
    if (t < 12) g_A1s[t] = g_sc[t >> 2] * g_A[(t >> 2) * 4 + (t & 3)];
}

__global__ void __launch_bounds__(64) k_pre_s1e(const float* __restrict__ feats,
                                                const float* __restrict__ sxw1) {
    int row = blockIdx.x, t = threadIdx.x;
    __shared__ float sf[61];
    if (t < 61) sf[t] = feats[(size_t)row * 61 + t] * g_sc[3 + t];
    __syncthreads();
    float acc = 0.f;
    #pragma unroll
    for (int c = 0; c < 61; c++) acc += sf[c] * sxw1[(3 + c) * 64 + t];
    g_s1pre[(size_t)row * 64 + t] = acc;
    if (t < 4) {
        float s = 0.f;
        #pragma unroll
        for (int c = 0; c < 61; c++) s += sf[c] * g_A[(3 + c) * 4 + t];
        g_epre[(size_t)row * 4 + t] = s;
    }
}

// ---------------------------------------------------------------------------
// Kernel 4: fused per-query pipeline (proven R2 version).
// 256 threads per (b,k). 32KB dyn smem.
//   buf: [0,4096) h1 -> lat[0,2048) + s1[2048,4096)
//        [4096,8192) h2 -> s2[4096,6144) + s3[6144,8192)
// ---------------------------------------------------------------------------
__global__ void __launch_bounds__(256, 4) k_main(
    const float* __restrict__ nxw1, const float* __restrict__ nxb1,
    const float* __restrict__ nxw2, const float* __restrict__ nxb2,
    const float* __restrict__ nxw3, const float* __restrict__ nxb3,
    const float* __restrict__ sxw2, const float* __restrict__ sxb2,
    const float* __restrict__ sxw3, const float* __restrict__ sxb3,
    float* __restrict__ out)
{
    float* sm = (float*)smraw;
    float* h1  = sm;
    float* h2  = sm + 4096;
    float* lat = sm;
    float* s1  = sm + 2048;
    float* s2  = sm + 4096;
    float* s3  = sm + 6144;
    __shared__ float rel_s[96];
    __shared__ int   sel_s[32];
    __shared__ float setf[64];
    __shared__ float gh[4];
    __shared__ float ebuf[128];
    __shared__ float wbuf[128];

    int bk = blockIdx.x;
    int t  = threadIdx.x;

    if (t < 32) sel_s[t] = g_selg[(size_t)bk * 32 + t];
    if (t >= 32 && t < 128) rel_s[t - 32] = g_rel[(size_t)bk * 96 + (t - 32)];
    __syncthreads();

    // Stage A: h1[n][j] = relu(h1pre[pt][j] + rel . w1[0:3][j] + b1[j])
    {
        int j  = t & 127;
        int nb = (t >> 7) * 16;
        float wr0 = nxw1[j], wr1 = nxw1[128 + j], wr2 = nxw1[256 + j], bj = nxb1[j];
        #pragma unroll
        for (int i = 0; i < 16; i++) {
            int n = nb + i;
            float acc = g_h1pre[(size_t)sel_s[n] * 128 + j] + bj
                      + rel_s[n * 3] * wr0 + rel_s[n * 3 + 1] * wr1 + rel_s[n * 3 + 2] * wr2;
            h1[n * 128 + j] = fmaxf(acc, 0.f);
        }
    }
    __syncthreads();

    // Stage B: h2 = relu(h1 @ nxw2 + b2)  [32 x 128], packed f32x2
    {
        int j0 = t & 63;
        int j1 = j0 + 64;
        int nb = (t >> 6) * 8;
        ull a0[8], a1[8];
        #pragma unroll
        for (int i = 0; i < 8; i++) { a0[i] = 0ull; a1[i] = 0ull; }
        for (int c = 0; c < 128; c += 4) {
            float wA0 = nxw2[c * 128 + j0],       wA1 = nxw2[(c + 1) * 128 + j0];
            float wA2 = nxw2[(c + 2) * 128 + j0], wA3 = nxw2[(c + 3) * 128 + j0];
            float wB0 = nxw2[c * 128 + j1],       wB1 = nxw2[(c + 1) * 128 + j1];
            float wB2 = nxw2[(c + 2) * 128 + j1], wB3 = nxw2[(c + 3) * 128 + j1];
            ull wa01 = pk2(wA0, wA1), wa23 = pk2(wA2, wA3);
            ull wb01 = pk2(wB0, wB1), wb23 = pk2(wB2, wB3);
            #pragma unroll
            for (int i = 0; i < 8; i++) {
                ulonglong2 x = *(const ulonglong2*)(h1 + (nb + i) * 128 + c);
                a0[i] = ffma2(x.x, wa01, a0[i]);
                a0[i] = ffma2(x.y, wa23, a0[i]);
                a1[i] = ffma2(x.x, wb01, a1[i]);
                a1[i] = ffma2(x.y, wb23, a1[i]);
            }
        }
        float b0 = nxb2[j0], b1v = nxb2[j1];
        #pragma unroll
        for (int i = 0; i < 8; i++) {
            h2[(nb + i) * 128 + j0] = fmaxf(hsum2(a0[i]) + b0, 0.f);
            h2[(nb + i) * 128 + j1] = fmaxf(hsum2(a1[i]) + b1v, 0.f);
        }
    }
    __syncthreads();

    // Stage C: lat = h2 @ nxw3 + b3  [32 x 64]
    {
        int o0 = t & 31;
        int o1 = o0 + 32;
        int nb = (t >> 5) * 4;
        ull a0[4], a1[4];
        #pragma unroll
        for (int i = 0; i < 4; i++) { a0[i] = 0ull; a1[i] = 0ull; }
        for (int c = 0; c < 128; c += 4) {
            float wA0 = nxw3[c * 64 + o0],       wA1 = nxw3[(c + 1) * 64 + o0];
            float wA2 = nxw3[(c + 2) * 64 + o0], wA3 = nxw3[(c + 3) * 64 + o0];
            float wB0 = nxw3[c * 64 + o1],       wB1 = nxw3[(c + 1) * 64 + o1];
            float wB2 = nxw3[(c + 2) * 64 + o1], wB3 = nxw3[(c + 3) * 64 + o1];
            ull wa01 = pk2(wA0, wA1), wa23 = pk2(wA2, wA3);
            ull wb01 = pk2(wB0, wB1), wb23 = pk2(wB2, wB3);
            #pragma unroll
            for (int i = 0; i < 4; i++) {
                ulonglong2 x = *(const ulonglong2*)(h2 + (nb + i) * 128 + c);
                a0[i] = ffma2(x.x, wa01, a0[i]);
                a0[i] = ffma2(x.y, wa23, a0[i]);
                a1[i] = ffma2(x.x, wb01, a1[i]);
                a1[i] = ffma2(x.y, wb23, a1[i]);
            }
        }
        float b0 = nxb3[o0], b1v = nxb3[o1];
        #pragma unroll
        for (int i = 0; i < 4; i++) {
            lat[(nb + i) * 64 + o0] = hsum2(a0[i]) + b0;
            lat[(nb + i) * 64 + o1] = hsum2(a1[i]) + b1v;
        }
    }
    __syncthreads();

    // Stage D: s1[n][o] = relu(s1pre[pt][o] + rel . Wr1s + C1[o])
    {
        int o  = t & 63;
        int nb = (t >> 6) * 8;
        float w0 = g_Wr1s[o], w1 = g_Wr1s[64 + o], w2 = g_Wr1s[128 + o], c1 = g_C1[o];
        #pragma unroll
        for (int i = 0; i < 8; i++) {
            int n = nb + i;
            float acc = g_s1pre[(size_t)sel_s[n] * 64 + o] + c1
                      + rel_s[n * 3] * w0 + rel_s[n * 3 + 1] * w1 + rel_s[n * 3 + 2] * w2;
            s1[n * 64 + o] = fmaxf(acc, 0.f);
        }
    }
    __syncthreads();

    // Stage E: s2 = relu(s1 @ sxw2 + b)  [32 x 64]
    {
        int o0 = t & 31;
        int o1 = o0 + 32;
        int nb = (t >> 5) * 4;
        ull a0[4], a1[4];
        #pragma unroll
        for (int i = 0; i < 4; i++) { a0[i] = 0ull; a1[i] = 0ull; }
        for (int c = 0; c < 64; c += 4) {
            float wA0 = sxw2[c * 64 + o0],       wA1 = sxw2[(c + 1) * 64 + o0];
            float wA2 = sxw2[(c + 2) * 64 + o0], wA3 = sxw2[(c + 3) * 64 + o0];
            float wB0 = sxw2[c * 64 + o1],       wB1 = sxw2[(c + 1) * 64 + o1];
            float wB2 = sxw2[(c + 2) * 64 + o1], wB3 = sxw2[(c + 3) * 64 + o1];
            ull wa01 = pk2(wA0, wA1), wa23 = pk2(wA2, wA3);
            ull wb01 = pk2(wB0, wB1), wb23 = pk2(wB2, wB3);
            #pragma unroll
            for (int i = 0; i < 4; i++) {
                ulonglong2 x = *(const ulonglong2*)(s1 + (nb + i) * 64 + c);
                a0[i] = ffma2(x.x, wa01, a0[i]);
                a0[i] = ffma2(x.y, wa23, a0[i]);
                a1[i] = ffma2(x.x, wb01, a1[i]);
                a1[i] = ffma2(x.y, wb23, a1[i]);
            }
        }
        float b0 = sxb2[o0], b1v = sxb2[o1];
        #pragma unroll
        for (int i = 0; i < 4; i++) {
            s2[(nb + i) * 64 + o0] = fmaxf(hsum2(a0[i]) + b0, 0.f);
            s2[(nb + i) * 64 + o1] = fmaxf(hsum2(a1[i]) + b1v, 0.f);
        }
    }
    __syncthreads();

    // Stage F: s3 = s2 @ sxw3 + b  (no relu)
    {
        int o0 = t & 31;
        int o1 = o0 + 32;
        int nb = (t >> 5) * 4;
        ull a0[4], a1[4];
        #pragma unroll
        for (int i = 0; i < 4; i++) { a0[i] = 0ull; a1[i] = 0ull; }
        for (int c = 0; c < 64; c += 4) {
            float wA0 = sxw3[c * 64 + o0],       wA1 = sxw3[(c + 1) * 64 + o0];
            float wA2 = sxw3[(c + 2) * 64 + o0], wA3 = sxw3[(c + 3) * 64 + o0];
            float wB0 = sxw3[c * 64 + o1],       wB1 = sxw3[(c + 1) * 64 + o1];
            float wB2 = sxw3[(c + 2) * 64 + o1], wB3 = sxw3[(c + 3) * 64 + o1];
            ull wa01 = pk2(wA0, wA1), wa23 = pk2(wA2, wA3);
            ull wb01 = pk2(wB0, wB1), wb23 = pk2(wB2, wB3);
            #pragma unroll
            for (int i = 0; i < 4; i++) {
                ulonglong2 x = *(const ulonglong2*)(s2 + (nb + i) * 64 + c);
                a0[i] = ffma2(x.x, wa01, a0[i]);
                a0[i] = ffma2(x.y, wa23, a0[i]);
                a1[i] = ffma2(x.x, wb01, a1[i]);
                a1[i] = ffma2(x.y, wb23, a1[i]);
            }
        }
        float b0 = sxb3[o0], b1v = sxb3[o1];
        #pragma unroll
        for (int i = 0; i < 4; i++) {
            s3[(nb + i) * 64 + o0] = hsum2(a0[i]) + b0;
            s3[(nb + i) * 64 + o1] = hsum2(a1[i]) + b1v;
        }
    }
    __syncthreads();

    // set_feat + folded head bias
    if (t < 64) {
        float s = 0.f;
        #pragma unroll
        for (int n = 0; n < 32; n++) s += s3[n * 64 + t];
        setf[t] = s;
    }
    __syncthreads();
    if (t < 4) {
        float s = g_Ce[t];
        #pragma unroll 8
        for (int c = 0; c < 64; c++) s += setf[c] * g_A[(64 + c) * 4 + t];
        gh[t] = s;
    }
    __syncthreads();

    // e[n][h] = gh[h] + epre[pt][h] + rel . A1s
    if (t < 128) {
        int n = t >> 2, h = t & 3;
        float e = gh[h] + g_epre[(size_t)sel_s[n] * 4 + h]
                + rel_s[n * 3] * g_A1s[h]
                + rel_s[n * 3 + 1] * g_A1s[4 + h]
                + rel_s[n * 3 + 2] * g_A1s[8 + h];
        ebuf[t] = e;
    }
    __syncthreads();

    // softmax over neighbor axis (per head)
    if (t < 4) {
        int h = t;
        float m = -INFINITY;
        #pragma unroll
        for (int n = 0; n < 32; n++) m = fmaxf(m, ebuf[n * 4 + h]);
        float s = 0.f;
        #pragma unroll
        for (int n = 0; n < 32; n++) {
            float ex = expf(ebuf[n * 4 + h] - m);
            wbuf[n * 4 + h] = ex;
            s += ex;
        }
        float inv = 1.f / s;
        #pragma unroll
        for (int n = 0; n < 32; n++) wbuf[n * 4 + h] *= inv;
    }
    __syncthreads();

    // out[o][h] = sum_n lat[n][o] * w[n][h]
    {
        int o = t >> 2, h = t & 3;
        float s = 0.f;
        #pragma unroll
        for (int n = 0; n < 32; n++) s += lat[n * 64 + o] * wbuf[n * 4 + h];
        out[(size_t)bk * 256 + t] = s;
    }
}

// ---------------------------------------------------------------------------
extern "C" void kernel_launch(void* const* d_in, const int* in_sizes, int n_in,
                              void* d_out, int out_size) {
    (void)in_sizes; (void)n_in; (void)out_size;
    const float* keys  = (const float*)d_in[0];
    const float* points= (const float*)d_in[1];
    const float* feats = (const float*)d_in[2];
    const float* nxw1  = (const float*)d_in[3];
    const float* nxb1  = (const float*)d_in[4];
    const float* nxw2  = (const float*)d_in[5];
    const float* nxb2  = (const float*)d_in[6];
    const float* nxw3  = (const float*)d_in[7];
    const float* nxb3  = (const float*)d_in[8];
    const float* sxw1  = (const float*)d_in[9];
    const float* sxb1  = (const float*)d_in[10];
    const float* sxw2  = (const float*)d_in[11];
    const float* sxb2  = (const float*)d_in[12];
    const float* sxw3  = (const float*)d_in[13];
    const float* sxb3  = (const float*)d_in[14];
    const float* attw  = (const float*)d_in[15];
    const float* attb  = (const float*)d_in[16];
    const float* attq  = (const float*)d_in[17];
    const float* gamma = (const float*)d_in[18];
    const float* beta  = (const float*)d_in[19];
    float* out = (float*)d_out;

    k_prep<<<2, 256>>>(attw, attb, attq);
    k_pre_h1<<<NPTS, 128>>>(feats, nxw1);
    k_knn<<<NBK, 256, 32768>>>(keys, points, feats);
    k_stats<<<64, 256>>>(gamma, beta);
    k_const<<<1, 256>>>(sxw1, sxb1);
    k_pre_s1e<<<NPTS, 64>>>(feats, sxw1);
    k_main<<<NBK, 256, 32768>>>(nxw1, nxb1, nxw2, nxb2, nxw3, nxb3,
                                sxw2, sxb2, sxw3, sxb3, out);
}

// round 7
// speedup vs baseline: 1.3433x; 1.0155x over previous
#include <cuda_runtime.h>
#include <math.h>
#include <stdint.h>

#define BB 4
#define KK 2048
#define NN 4096
#define CIN 61
#define NBK (BB*KK)
#define NPTS (BB*NN)
#define KNBR 32
#define CNTF 262144.0

typedef unsigned long long ull;

// Scratch (static device globals — allocation-free)
__device__ float g_part[(size_t)128 * NBK];     // transposed BN partials [c][bk]
__device__ float g_A[516];
__device__ int   g_selg[(size_t)NBK * KNBR];
__device__ float g_rel[(size_t)NBK * KNBR * 3];
__device__ float g_h1pre[(size_t)NPTS * 128];
__device__ float g_s1pre[(size_t)NPTS * 64];
__device__ float g_epre[(size_t)NPTS * 4];
__device__ float g_sc[64], g_tc[64];
__device__ float g_C1[64], g_Ce[4];
__device__ float g_Wr1s[192], g_A1s[12];
// packed f32x2 weight pairs: wpk[c/2][o] = (w[c][o], w[c+1][o])
__device__ ull g_w2p[8192];    // nxw2 128x128 -> [64][128]
__device__ ull g_w3p[4096];    // nxw3 128x64  -> [64][64]
__device__ ull g_sw2p[2048];   // sxw2 64x64   -> [32][64]
__device__ ull g_sw3p[2048];   // sxw3 64x64   -> [32][64]

__device__ __forceinline__ ull ffma2(ull a, ull b, ull c) {
    ull d; asm("fma.rn.f32x2 %0, %1, %2, %3;" : "=l"(d) : "l"(a), "l"(b), "l"(c)); return d;
}
__device__ __forceinline__ ull pk2(float lo, float hi) {
    ull d; asm("mov.b64 %0, {%1, %2};" : "=l"(d) : "f"(lo), "f"(hi)); return d;
}
__device__ __forceinline__ float hsum2(ull a) {
    float lo, hi;
    asm("mov.b64 {%0, %1}, %2;" : "=f"(lo), "=f"(hi) : "l"(a));
    return lo + hi;
}

// ---------------------------------------------------------------------------
__global__ void k_prep(const float* __restrict__ att_w, const float* __restrict__ att_b,
                       const float* __restrict__ att_q) {
    int t = blockIdx.x * blockDim.x + threadIdx.x;
    if (t < 512) {
        int c = t >> 2, h = t & 3;
        float s = 0.f;
        #pragma unroll 8
        for (int o = 0; o < 64; o++) s += att_w[c * 256 + h * 64 + o] * att_q[h * 64 + o];
        g_A[t] = s;
    }
    if (t < 4) {
        float s = 0.f;
        #pragma unroll 8
        for (int o = 0; o < 64; o++) s += att_b[t * 64 + o] * att_q[t * 64 + o];
        g_A[512 + t] = s;
    }
}

// pack weights into f32x2 pairs (exact bit repacking)
__global__ void __launch_bounds__(256) k_pack(const float* __restrict__ nxw2,
                                              const float* __restrict__ nxw3,
                                              const float* __restrict__ sxw2,
                                              const float* __restrict__ sxw3) {
    int t = blockIdx.x * blockDim.x + threadIdx.x;   // 0..16383
    if (t < 8192) {
        int r = t >> 7, j = t & 127;
        g_w2p[t] = pk2(nxw2[(2 * r) * 128 + j], nxw2[(2 * r + 1) * 128 + j]);
    } else if (t < 12288) {
        int i = t - 8192, r = i >> 6, o = i & 63;
        g_w3p[i] = pk2(nxw3[(2 * r) * 64 + o], nxw3[(2 * r + 1) * 64 + o]);
    } else if (t < 14336) {
        int i = t - 12288, r = i >> 6, o = i & 63;
        g_sw2p[i] = pk2(sxw2[(2 * r) * 64 + o], sxw2[(2 * r + 1) * 64 + o]);
    } else {
        int i = t - 14336, r = i >> 6, o = i & 63;
        g_sw3p[i] = pk2(sxw3[(2 * r) * 64 + o], sxw3[(2 * r + 1) * 64 + o]);
    }
}

__global__ void __launch_bounds__(128) k_pre_h1(const float* __restrict__ feats,
                                                const float* __restrict__ nxw1) {
    int row = blockIdx.x, t = threadIdx.x;
    __shared__ float f[61];
    if (t < 61) f[t] = feats[(size_t)row * 61 + t];
    __syncthreads();
    float acc = 0.f;
    #pragma unroll
    for (int c = 0; c < 61; c++) acc += f[c] * nxw1[(3 + c) * 128 + t];
    g_h1pre[(size_t)row * 128 + t] = acc;
}

// block exclusive scan (256 threads)
__device__ __forceinline__ uint blk_scan_excl(uint val, volatile uint* ws, uint* tot) {
    __syncthreads();
    int lane = threadIdx.x & 31, w = threadIdx.x >> 5;
    uint inc = val;
    #pragma unroll
    for (int o = 1; o < 32; o <<= 1) {
        uint x = __shfl_up_sync(0xffffffffu, inc, o);
        if (lane >= o) inc += x;
    }
    if (lane == 31) ws[w] = inc;
    __syncthreads();
    if (threadIdx.x == 0) {
        uint run = 0;
        for (int i = 0; i < 8; i++) { uint x = ws[i]; ws[i] = run; run += x; }
        ws[8] = run;
    }
    __syncthreads();
    if (tot) *tot = ws[8];
    return inc - val + ws[w];
}

extern __shared__ char smraw[];

// ---------------------------------------------------------------------------
// kNN via radix-select. dyn smem 32KB: d2u[4096] | hist[2048] | cand ushort[4096]
// ---------------------------------------------------------------------------
__global__ void __launch_bounds__(256) k_knn(const float* __restrict__ keys,
                                             const float* __restrict__ points,
                                             const float* __restrict__ feats) {
    uint* smu  = (uint*)smraw;
    uint* d2u  = smu;
    uint* hist = smu + 4096;
    unsigned short* cand = (unsigned short*)(smu + 6144);

    __shared__ int  sel[KNBR];
    __shared__ uint ws[9];
    __shared__ int  sP1, sM1, sP2, sM2;
    __shared__ ull  wmin[8];

    int bk = blockIdx.x, b = bk >> 11, k = bk & 2047, tid = threadIdx.x;

    float kx = keys[(b * KK + k) * 3 + 0];
    float ky = keys[(b * KK + k) * 3 + 1];
    float kz = keys[(b * KK + k) * 3 + 2];
    const float* pb = points + (size_t)b * NN * 3;

    #pragma unroll
    for (int j = 0; j < 8; j++) hist[tid + j * 256] = 0;
    __syncthreads();

    #pragma unroll
    for (int j = 0; j < 16; j++) {
        int p = tid + j * 256;
        float dx = pb[p * 3 + 0] - kx;
        float dy = pb[p * 3 + 1] - ky;
        float dz = pb[p * 3 + 2] - kz;
        uint u = __float_as_uint(dx * dx + dy * dy + dz * dz);
        d2u[p] = u;
        atomicAdd(&hist[u >> 21], 1u);
    }
    __syncthreads();

    // pass 1: find 11-bit pivot bin
    {
        uint cnt8[8], s = 0;
        #pragma unroll
        for (int j = 0; j < 8; j++) { cnt8[j] = hist[tid * 8 + j]; s += cnt8[j]; }
        uint e = blk_scan_excl(s, ws, 0);
        if (e < KNBR && e + s >= KNBR) {
            uint cum = e;
            #pragma unroll
            for (int j = 0; j < 8; j++) {
                if (cum + cnt8[j] >= KNBR) { sP1 = tid * 8 + j; sM1 = (int)cum; break; }
                cum += cnt8[j];
            }
        }
    }
    __syncthreads();
    int P1 = sP1, m1 = sM1;

    // pass 2: 8-bit refine inside bin P1
    hist[tid] = 0;
    __syncthreads();
    #pragma unroll
    for (int j = 0; j < 16; j++) {
        int p = tid + j * 256;
        uint u = d2u[p];
        if ((int)(u >> 21) == P1) atomicAdd(&hist[(u >> 13) & 255], 1u);
    }
    __syncthreads();
    {
        uint v = hist[tid];
        uint e = blk_scan_excl(v, ws, 0);
        int need1 = KNBR - m1;
        if ((int)e < need1 && (int)(e + v) >= need1) { sP2 = tid; sM2 = (int)e; }
    }
    __syncthreads();
    int P2 = sP2, m2 = sM2;

    // compaction: strictly-below -> sel, boundary -> cand
    uint tot = 0;
    {
        uint fb = 0, fe = 0;
        #pragma unroll
        for (int j = 0; j < 16; j++) {
            int p = tid + j * 256;
            uint u = d2u[p];
            int b1 = (int)(u >> 21);
            if (b1 < P1) fb |= (1u << j);
            else if (b1 == P1) {
                int b2 = (int)((u >> 13) & 255);
                if (b2 < P2) fb |= (1u << j);
                else if (b2 == P2) fe |= (1u << j);
            }
        }
        uint packed = ((uint)__popc(fb) << 16) | (uint)__popc(fe);
        uint e = blk_scan_excl(packed, ws, &tot);
        int bB = (int)(e >> 16), bE = (int)(e & 0xFFFF);
        #pragma unroll
        for (int j = 0; j < 16; j++) {
            int p = tid + j * 256;
            if (fb & (1u << j)) sel[bB++] = p;
            if (fe & (1u << j)) cand[bE++] = (unsigned short)p;
        }
    }
    __syncthreads();

    // argmin rounds on boundary candidates (deterministic tie-break: lowest idx)
    {
        int m = m1 + m2, need = KNBR - m, cc = (int)(tot & 0xFFFF);
        for (int r = 0; r < need; r++) {
            ull best = ~0ull;
            for (int i = tid; i < cc; i += 256) {
                int p = cand[i];
                ull key = ((ull)d2u[p] << 32) | (uint)p;
                if (key < best) best = key;
            }
            #pragma unroll
            for (int off = 16; off; off >>= 1) {
                ull o = __shfl_down_sync(0xffffffffu, best, off);
                if (o < best) best = o;
            }
            if ((tid & 31) == 0) wmin[tid >> 5] = best;
            __syncthreads();
            if (tid == 0) {
                ull bb = wmin[0];
                #pragma unroll
                for (int w = 1; w < 8; w++) if (wmin[w] < bb) bb = wmin[w];
                int p = (int)(bb & 0xFFFFFFFFull);
                sel[m + r] = p;
                d2u[p] = 0xFFFFFFFFu;
            }
            __syncthreads();
        }
    }

    // gather comb (reuse d2u region as float cs[2048])
    float* cs = (float*)smu;
    const float* fb2 = feats + (size_t)b * NN * CIN;
    __syncthreads();
    #pragma unroll
    for (int j = 0; j < 8; j++) {
        int e = tid + j * 256;
        int n = e >> 6, c = e & 63;
        int p = sel[n];
        float v;
        if (c < 3) {
            float kc = (c == 0) ? kx : ((c == 1) ? ky : kz);
            v = pb[p * 3 + c] - kc;
        } else v = fb2[p * CIN + (c - 3)];
        cs[e] = v;
    }
    __syncthreads();

    if (tid < 64) {
        float s = 0.f, ss = 0.f;
        #pragma unroll
        for (int n = 0; n < KNBR; n++) { float v = cs[n * 64 + tid]; s += v; ss += v * v; }
        g_part[(size_t)tid * NBK + bk]        = s;
        g_part[(size_t)(64 + tid) * NBK + bk] = ss;
    }
    if (tid < 32) g_selg[(size_t)bk * 32 + tid] = b * NN + sel[tid];
    if (tid < 96) g_rel[(size_t)bk * 96 + tid] = cs[(tid / 3) * 64 + (tid % 3)];
}

// ---------------------------------------------------------------------------
__global__ void __launch_bounds__(256) k_stats(const float* __restrict__ gamma,
                                               const float* __restrict__ beta) {
    int c = blockIdx.x, t = threadIdx.x;
    double s = 0.0, ss = 0.0;
    const float* ps  = g_part + (size_t)c * NBK;
    const float* pss = g_part + (size_t)(64 + c) * NBK;
    for (int i = t; i < NBK; i += 256) { s += (double)ps[i]; ss += (double)pss[i]; }
    __shared__ double rs[256], rss[256];
    rs[t] = s; rss[t] = ss;
    __syncthreads();
    for (int o = 128; o; o >>= 1) {
        if (t < o) { rs[t] += rs[t + o]; rss[t] += rss[t + o]; }
        __syncthreads();
    }
    if (t == 0) {
        double mean = rs[0] / CNTF;
        double var  = rss[0] / CNTF - mean * mean;
        float sc = (float)((1.0 / sqrt(var + 1e-5)) * (double)gamma[c]);
        g_sc[c] = sc;
        g_tc[c] = beta[c] - (float)mean * sc;
    }
}

__global__ void k_const(const float* __restrict__ sxw1, const float* __restrict__ sxb1) {
    int t = threadIdx.x;
    if (t < 64) {
        float s = sxb1[t];
        #pragma unroll 8
        for (int c = 0; c < 64; c++) s += g_tc[c] * sxw1[c * 64 + t];
        g_C1[t] = s;
    }
    if (t < 4) {
        float s = g_A[512 + t];
        #pragma unroll 8
        for (int c = 0; c < 64; c++) s += g_tc[c] * g_A[c * 4 + t];
        g_Ce[t] = s;
    }
    if (t >= 64) {
        int i = t - 64, c = i >> 6, o = i & 63;
        g_Wr1s[i] = g_sc[c] * sxw1[c * 64 + o];
    }
    if (t < 12) g_A1s[t] = g_sc[t >> 2] * g_A[(t >> 2) * 4 + (t & 3)];
}

__global__ void __launch_bounds__(64) k_pre_s1e(const float* __restrict__ feats,
                                                const float* __restrict__ sxw1) {
    int row = blockIdx.x, t = threadIdx.x;
    __shared__ float sf[61];
    if (t < 61) sf[t] = feats[(size_t)row * 61 + t] * g_sc[3 + t];
    __syncthreads();
    float acc = 0.f;
    #pragma unroll
    for (int c = 0; c < 61; c++) acc += sf[c] * sxw1[(3 + c) * 64 + t];
    g_s1pre[(size_t)row * 64 + t] = acc;
    if (t < 4) {
        float s = 0.f;
        #pragma unroll
        for (int c = 0; c < 61; c++) s += sf[c] * g_A[(3 + c) * 4 + t];
        g_epre[(size_t)row * 4 + t] = s;
    }
}

// ---------------------------------------------------------------------------
// Kernel 4: fused per-query pipeline, packed-weight GEMM stages.
// 256 threads per (b,k). 32KB dyn smem.
//   buf: [0,4096) h1 -> lat[0,2048) + s1[2048,4096)
//        [4096,8192) h2 -> s2[4096,6144) + s3[6144,8192)
// ---------------------------------------------------------------------------
__global__ void __launch_bounds__(256, 4) k_main(
    const float* __restrict__ nxw1, const float* __restrict__ nxb1,
    const float* __restrict__ nxb2, const float* __restrict__ nxb3,
    const float* __restrict__ sxb2, const float* __restrict__ sxb3,
    float* __restrict__ out)
{
    float* sm = (float*)smraw;
    float* h1  = sm;
    float* h2  = sm + 4096;
    float* lat = sm;
    float* s1  = sm + 2048;
    float* s2  = sm + 4096;
    float* s3  = sm + 6144;
    __shared__ float rel_s[96];
    __shared__ int   sel_s[32];
    __shared__ float setf[64];
    __shared__ float gh[4];
    __shared__ float ebuf[128];
    __shared__ float wbuf[128];

    int bk = blockIdx.x;
    int t  = threadIdx.x;

    if (t < 32) sel_s[t] = g_selg[(size_t)bk * 32 + t];
    if (t >= 32 && t < 128) rel_s[t - 32] = g_rel[(size_t)bk * 96 + (t - 32)];
    __syncthreads();

    // Stage A: h1[n][j] = relu(h1pre[pt][j] + rel . w1[0:3][j] + b1[j])
    {
        int j  = t & 127;
        int nb = (t >> 7) * 16;
        float wr0 = nxw1[j], wr1 = nxw1[128 + j], wr2 = nxw1[256 + j], bj = nxb1[j];
        #pragma unroll
        for (int i = 0; i < 16; i++) {
            int n = nb + i;
            float acc = g_h1pre[(size_t)sel_s[n] * 128 + j] + bj
                      + rel_s[n * 3] * wr0 + rel_s[n * 3 + 1] * wr1 + rel_s[n * 3 + 2] * wr2;
            h1[n * 128 + j] = fmaxf(acc, 0.f);
        }
    }
    __syncthreads();

    // Stage B: h2 = relu(h1 @ nxw2 + b2)  [32 x 128], packed weights
    {
        int j0 = t & 63;
        int j1 = j0 + 64;
        int nb = (t >> 6) * 8;
        ull a0[8], a1[8];
        #pragma unroll
        for (int i = 0; i < 8; i++) { a0[i] = 0ull; a1[i] = 0ull; }
        for (int c = 0; c < 128; c += 4) {
            const ull* wp = g_w2p + (c >> 1) * 128;
            ull wa01 = wp[j0],       wb01 = wp[j1];
            ull wa23 = wp[128 + j0], wb23 = wp[128 + j1];
            #pragma unroll
            for (int i = 0; i < 8; i++) {
                ulonglong2 x = *(const ulonglong2*)(h1 + (nb + i) * 128 + c);
                a0[i] = ffma2(x.x, wa01, a0[i]);
                a0[i] = ffma2(x.y, wa23, a0[i]);
                a1[i] = ffma2(x.x, wb01, a1[i]);
                a1[i] = ffma2(x.y, wb23, a1[i]);
            }
        }
        float b0 = nxb2[j0], b1v = nxb2[j1];
        #pragma unroll
        for (int i = 0; i < 8; i++) {
            h2[(nb + i) * 128 + j0] = fmaxf(hsum2(a0[i]) + b0, 0.f);
            h2[(nb + i) * 128 + j1] = fmaxf(hsum2(a1[i]) + b1v, 0.f);
        }
    }
    __syncthreads();

    // Stage C: lat = h2 @ nxw3 + b3  [32 x 64]
    {
        int o0 = t & 31;
        int o1 = o0 + 32;
        int nb = (t >> 5) * 4;
        ull a0[4], a1[4];
        #pragma unroll
        for (int i = 0; i < 4; i++) { a0[i] = 0ull; a1[i] = 0ull; }
        for (int c = 0; c < 128; c += 4) {
            const ull* wp = g_w3p + (c >> 1) * 64;
            ull wa01 = wp[o0],      wb01 = wp[o1];
            ull wa23 = wp[64 + o0], wb23 = wp[64 + o1];
            #pragma unroll
            for (int i = 0; i < 4; i++) {
                ulonglong2 x = *(const ulonglong2*)(h2 + (nb + i) * 128 + c);
                a0[i] = ffma2(x.x, wa01, a0[i]);
                a0[i] = ffma2(x.y, wa23, a0[i]);
                a1[i] = ffma2(x.x, wb01, a1[i]);
                a1[i] = ffma2(x.y, wb23, a1[i]);
            }
        }
        float b0 = nxb3[o0], b1v = nxb3[o1];
        #pragma unroll
        for (int i = 0; i < 4; i++) {
            lat[(nb + i) * 64 + o0] = hsum2(a0[i]) + b0;
            lat[(nb + i) * 64 + o1] = hsum2(a1[i]) + b1v;
        }
    }
    __syncthreads();

    // Stage D: s1[n][o] = relu(s1pre[pt][o] + rel . Wr1s + C1[o])
    {
        int o  = t & 63;
        int nb = (t >> 6) * 8;
        float w0 = g_Wr1s[o], w1 = g_Wr1s[64 + o], w2 = g_Wr1s[128 + o], c1 = g_C1[o];
        #pragma unroll
        for (int i = 0; i < 8; i++) {
            int n = nb + i;
            float acc = g_s1pre[(size_t)sel_s[n] * 64 + o] + c1
                      + rel_s[n * 3] * w0 + rel_s[n * 3 + 1] * w1 + rel_s[n * 3 + 2] * w2;
            s1[n * 64 + o] = fmaxf(acc, 0.f);
        }
    }
    __syncthreads();

    // Stage E: s2 = relu(s1 @ sxw2 + b)  [32 x 64]
    {
        int o0 = t & 31;
        int o1 = o0 + 32;
        int nb = (t >> 5) * 4;
        ull a0[4], a1[4];
        #pragma unroll
        for (int i = 0; i < 4; i++) { a0[i] = 0ull; a1[i] = 0ull; }
        for (int c = 0; c < 64; c += 4) {
            const ull* wp = g_sw2p + (c >> 1) * 64;
            ull wa01 = wp[o0],      wb01 = wp[o1];
            ull wa23 = wp[64 + o0], wb23 = wp[64 + o1];
            #pragma unroll
            for (int i = 0; i < 4; i++) {
                ulonglong2 x = *(const ulonglong2*)(s1 + (nb + i) * 64 + c);
                a0[i] = ffma2(x.x, wa01, a0[i]);
                a0[i] = ffma2(x.y, wa23, a0[i]);
                a1[i] = ffma2(x.x, wb01, a1[i]);
                a1[i] = ffma2(x.y, wb23, a1[i]);
            }
        }
        float b0 = sxb2[o0], b1v = sxb2[o1];
        #pragma unroll
        for (int i = 0; i < 4; i++) {
            s2[(nb + i) * 64 + o0] = fmaxf(hsum2(a0[i]) + b0, 0.f);
            s2[(nb + i) * 64 + o1] = fmaxf(hsum2(a1[i]) + b1v, 0.f);
        }
    }
    __syncthreads();

    // Stage F: s3 = s2 @ sxw3 + b  (no relu)
    {
        int o0 = t & 31;
        int o1 = o0 + 32;
        int nb = (t >> 5) * 4;
        ull a0[4], a1[4];
        #pragma unroll
        for (int i = 0; i < 4; i++) { a0[i] = 0ull; a1[i] = 0ull; }
        for (int c = 0; c < 64; c += 4) {
            const ull* wp = g_sw3p + (c >> 1) * 64;
            ull wa01 = wp[o0],      wb01 = wp[o1];
            ull wa23 = wp[64 + o0], wb23 = wp[64 + o1];
            #pragma unroll
            for (int i = 0; i < 4; i++) {
                ulonglong2 x = *(const ulonglong2*)(s2 + (nb + i) * 64 + c);
                a0[i] = ffma2(x.x, wa01, a0[i]);
                a0[i] = ffma2(x.y, wa23, a0[i]);
                a1[i] = ffma2(x.x, wb01, a1[i]);
                a1[i] = ffma2(x.y, wb23, a1[i]);
            }
        }
        float b0 = sxb3[o0], b1v = sxb3[o1];
        #pragma unroll
        for (int i = 0; i < 4; i++) {
            s3[(nb + i) * 64 + o0] = hsum2(a0[i]) + b0;
            s3[(nb + i) * 64 + o1] = hsum2(a1[i]) + b1v;
        }
    }
    __syncthreads();

    // set_feat + folded head bias
    if (t < 64) {
        float s = 0.f;
        #pragma unroll
        for (int n = 0; n < 32; n++) s += s3[n * 64 + t];
        setf[t] = s;
    }
    __syncthreads();
    if (t < 4) {
        float s = g_Ce[t];
        #pragma unroll 8
        for (int c = 0; c < 64; c++) s += setf[c] * g_A[(64 + c) * 4 + t];
        gh[t] = s;
    }
    __syncthreads();

    // e[n][h] = gh[h] + epre[pt][h] + rel . A1s
    if (t < 128) {
        int n = t >> 2, h = t & 3;
        float e = gh[h] + g_epre[(size_t)sel_s[n] * 4 + h]
                + rel_s[n * 3] * g_A1s[h]
                + rel_s[n * 3 + 1] * g_A1s[4 + h]
                + rel_s[n * 3 + 2] * g_A1s[8 + h];
        ebuf[t] = e;
    }
    __syncthreads();

    // softmax over neighbor axis (per head)
    if (t < 4) {
        int h = t;
        float m = -INFINITY;
        #pragma unroll
        for (int n = 0; n < 32; n++) m = fmaxf(m, ebuf[n * 4 + h]);
        float s = 0.f;
        #pragma unroll
        for (int n = 0; n < 32; n++) {
            float ex = expf(ebuf[n * 4 + h] - m);
            wbuf[n * 4 + h] = ex;
            s += ex;
        }
        float inv = 1.f / s;
        #pragma unroll
        for (int n = 0; n < 32; n++) wbuf[n * 4 + h] *= inv;
    }
    __syncthreads();

    // out[o][h] = sum_n lat[n][o] * w[n][h]
    {
        int o = t >> 2, h = t & 3;
        float s = 0.f;
        #pragma unroll
        for (int n = 0; n < 32; n++) s += lat[n * 64 + o] * wbuf[n * 4 + h];
        out[(size_t)bk * 256 + t] = s;
    }
}

// ---------------------------------------------------------------------------
extern "C" void kernel_launch(void* const* d_in, const int* in_sizes, int n_in,
                              void* d_out, int out_size) {
    (void)in_sizes; (void)n_in; (void)out_size;
    const float* keys  = (const float*)d_in[0];
    const float* points= (const float*)d_in[1];
    const float* feats = (const float*)d_in[2];
    const float* nxw1  = (const float*)d_in[3];
    const float* nxb1  = (const float*)d_in[4];
    const float* nxw2  = (const float*)d_in[5];
    const float* nxb2  = (const float*)d_in[6];
    const float* nxw3  = (const float*)d_in[7];
    const float* nxb3  = (const float*)d_in[8];
    const float* sxw1  = (const float*)d_in[9];
    const float* sxb1  = (const float*)d_in[10];
    const float* sxw2  = (const float*)d_in[11];
    const float* sxb2  = (const float*)d_in[12];
    const float* sxw3  = (const float*)d_in[13];
    const float* sxb3  = (const float*)d_in[14];
    const float* attw  = (const float*)d_in[15];
    const float* attb  = (const float*)d_in[16];
    const float* attq  = (const float*)d_in[17];
    const float* gamma = (const float*)d_in[18];
    const float* beta  = (const float*)d_in[19];
    float* out = (float*)d_out;

    k_prep<<<2, 256>>>(attw, attb, attq);
    k_pack<<<64, 256>>>(nxw2, nxw3, sxw2, sxw3);
    k_pre_h1<<<NPTS, 128>>>(feats, nxw1);
    k_knn<<<NBK, 256, 32768>>>(keys, points, feats);
    k_stats<<<64, 256>>>(gamma, beta);
    k_const<<<1, 256>>>(sxw1, sxb1);
    k_pre_s1e<<<NPTS, 64>>>(feats, sxw1);
    k_main<<<NBK, 256, 32768>>>(nxw1, nxb1, nxb2, nxb3, sxb2, sxb3, out);
}

// round 9
// speedup vs baseline: 1.7111x; 1.2738x over previous
#include <cuda_runtime.h>
#include <cuda_bf16.h>
#include <math.h>
#include <stdint.h>

#define BB 4
#define KK 2048
#define NN 4096
#define CIN 61
#define NBK (BB*KK)
#define NPTS (BB*NN)
#define KNBR 32
#define CNTF 262144.0

typedef unsigned long long ull;

// ---------------- scratch globals ----------------
__device__ float g_part[(size_t)128 * NBK];
__device__ float g_A[516];
__device__ int   g_selg[(size_t)NBK * KNBR];
__device__ float g_rel[(size_t)NBK * KNBR * 3];
__device__ float g_h1pre[(size_t)NPTS * 128];
__device__ float g_s1pre[(size_t)NPTS * 64];
__device__ float g_epre[(size_t)NPTS * 4];
__device__ float g_sc[64], g_tc[64];
__device__ float g_C1[64], g_Ce[4];
__device__ float g_Wr1s[192], g_A1s[12];
// transposed padded bf16 hi/lo weights: [n][k] row-major, pitch 136 (big) / 72 (small)
__device__ __align__(16) __nv_bfloat16 g_W2h[128*136], g_W2l[128*136];
__device__ __align__(16) __nv_bfloat16 g_W3h[64*136],  g_W3l[64*136];
__device__ __align__(16) __nv_bfloat16 g_S2h[64*72],   g_S2l[64*72];
__device__ __align__(16) __nv_bfloat16 g_S3h[64*72],   g_S3l[64*72];

// ---------------- helpers ----------------
__device__ __forceinline__ void mma16816(float* d, const uint32_t* a, uint32_t b0, uint32_t b1) {
    asm volatile("mma.sync.aligned.m16n8k16.row.col.f32.bf16.bf16.f32 "
        "{%0,%1,%2,%3}, {%4,%5,%6,%7}, {%8,%9}, {%0,%1,%2,%3};"
        : "+f"(d[0]), "+f"(d[1]), "+f"(d[2]), "+f"(d[3])
        : "r"(a[0]), "r"(a[1]), "r"(a[2]), "r"(a[3]), "r"(b0), "r"(b1));
}
// pack (v0,v1) -> bf16x2 hi + bf16x2 residual-lo, store 32b each
__device__ __forceinline__ void split_store(float v0, float v1, char* pH, char* pL) {
    uint32_t h;
    asm("cvt.rn.bf16x2.f32 %0, %1, %2;" : "=r"(h) : "f"(v1), "f"(v0));  // lo16=v0, hi16=v1
    float r0 = v0 - __uint_as_float(h << 16);
    float r1 = v1 - __uint_as_float(h & 0xFFFF0000u);
    uint32_t lo;
    asm("cvt.rn.bf16x2.f32 %0, %1, %2;" : "=r"(lo) : "f"(r1), "f"(r0));
    *(uint32_t*)pH = h;
    *(uint32_t*)pL = lo;
}

#define XP 136   // activation tile pitch (bf16 elems)
// dyn smem byte offsets
#define O_XH   0
#define O_XL   34816
#define O_W2H  69632
#define O_W2L  104448
#define O_W3H  139264
#define O_W3L  156672
#define O_S2H  174080
#define O_S2L  183296
#define O_S3H  192512
#define O_S3L  201728
#define SM_TOTAL 210944
#define O_LAT  69632    // fp32 [128][68], overlays dead W2H after stage B
#define O_S3F  104448   // fp32 [128][68], overlays dead W2L
#define LP 68

extern __shared__ char smraw[];

// MMA stage: A = X tile (hi/lo, pitch XP), B = W tile (hi/lo, pitch wpitch)
template<int KT, int NT, int WPITCH>
__device__ __forceinline__ void run_mma(const char* XHp, const char* XLp,
                                        const char* WHp, const char* WLp,
                                        float (&acc)[NT][4], int m0, int gid, int tig) {
    #pragma unroll
    for (int kt = 0; kt < KT; kt++) {
        int k0 = kt * 16 + 2 * tig;
        const char* xa0 = XHp + ((m0 + gid) * XP + k0) * 2;
        const char* xa1 = XHp + ((m0 + gid + 8) * XP + k0) * 2;
        const char* xb0 = XLp + ((m0 + gid) * XP + k0) * 2;
        const char* xb1 = XLp + ((m0 + gid + 8) * XP + k0) * 2;
        uint32_t ah[4], al[4];
        ah[0] = *(const uint32_t*)xa0;        ah[1] = *(const uint32_t*)xa1;
        ah[2] = *(const uint32_t*)(xa0 + 16); ah[3] = *(const uint32_t*)(xa1 + 16);
        al[0] = *(const uint32_t*)xb0;        al[1] = *(const uint32_t*)xb1;
        al[2] = *(const uint32_t*)(xb0 + 16); al[3] = *(const uint32_t*)(xb1 + 16);
        #pragma unroll
        for (int nt = 0; nt < NT; nt++) {
            int n = nt * 8 + gid;
            const char* bh = WHp + (n * WPITCH + k0) * 2;
            const char* bl = WLp + (n * WPITCH + k0) * 2;
            uint32_t bh0 = *(const uint32_t*)bh, bh1 = *(const uint32_t*)(bh + 16);
            uint32_t bl0 = *(const uint32_t*)bl, bl1 = *(const uint32_t*)(bl + 16);
            mma16816(acc[nt], ah, bh0, bh1);
            mma16816(acc[nt], ah, bl0, bl1);
            mma16816(acc[nt], al, bh0, bh1);
        }
    }
}

// ---------------------------------------------------------------------------
__global__ void k_prep(const float* __restrict__ att_w, const float* __restrict__ att_b,
                       const float* __restrict__ att_q) {
    int t = blockIdx.x * blockDim.x + threadIdx.x;
    if (t < 512) {
        int c = t >> 2, h = t & 3;
        float s = 0.f;
        #pragma unroll 8
        for (int o = 0; o < 64; o++) s += att_w[c * 256 + h * 64 + o] * att_q[h * 64 + o];
        g_A[t] = s;
    }
    if (t < 4) {
        float s = 0.f;
        #pragma unroll 8
        for (int o = 0; o < 64; o++) s += att_b[t * 64 + o] * att_q[t * 64 + o];
        g_A[512 + t] = s;
    }
}

// pack weights: transpose to [n][k], pad pitch, split bf16 hi/lo
__global__ void __launch_bounds__(256) k_packw(const float* __restrict__ nxw2,
                                               const float* __restrict__ nxw3,
                                               const float* __restrict__ sxw2,
                                               const float* __restrict__ sxw3) {
    int t = blockIdx.x * blockDim.x + threadIdx.x;   // 0..32767
    float v; int idx; __nv_bfloat16 *dh, *dl;
    if (t < 16384) {
        int j = t >> 7, c = t & 127;
        v = nxw2[c * 128 + j]; idx = j * 136 + c; dh = g_W2h; dl = g_W2l;
    } else if (t < 24576) {
        int i = t - 16384, o = i >> 7, c = i & 127;
        v = nxw3[c * 64 + o]; idx = o * 136 + c; dh = g_W3h; dl = g_W3l;
    } else if (t < 28672) {
        int i = t - 24576, o = i >> 6, c = i & 63;
        v = sxw2[c * 64 + o]; idx = o * 72 + c; dh = g_S2h; dl = g_S2l;
    } else {
        int i = t - 28672, o = i >> 6, c = i & 63;
        v = sxw3[c * 64 + o]; idx = o * 72 + c; dh = g_S3h; dl = g_S3l;
    }
    __nv_bfloat16 hv = __float2bfloat16(v);
    __nv_bfloat16 lv = __float2bfloat16(v - __bfloat162float(hv));
    dh[idx] = hv; dl[idx] = lv;
}

__global__ void __launch_bounds__(128) k_pre_h1(const float* __restrict__ feats,
                                                const float* __restrict__ nxw1) {
    int row = blockIdx.x, t = threadIdx.x;
    __shared__ float f[61];
    if (t < 61) f[t] = feats[(size_t)row * 61 + t];
    __syncthreads();
    float acc = 0.f;
    #pragma unroll
    for (int c = 0; c < 61; c++) acc += f[c] * nxw1[(3 + c) * 128 + t];
    g_h1pre[(size_t)row * 128 + t] = acc;
}

__device__ __forceinline__ uint blk_scan_excl(uint val, volatile uint* ws, uint* tot) {
    __syncthreads();
    int lane = threadIdx.x & 31, w = threadIdx.x >> 5;
    uint inc = val;
    #pragma unroll
    for (int o = 1; o < 32; o <<= 1) {
        uint x = __shfl_up_sync(0xffffffffu, inc, o);
        if (lane >= o) inc += x;
    }
    if (lane == 31) ws[w] = inc;
    __syncthreads();
    if (threadIdx.x == 0) {
        uint run = 0;
        for (int i = 0; i < 8; i++) { uint x = ws[i]; ws[i] = run; run += x; }
        ws[8] = run;
    }
    __syncthreads();
    if (tot) *tot = ws[8];
    return inc - val + ws[w];
}

// ---------------------------------------------------------------------------
__global__ void __launch_bounds__(256) k_knn(const float* __restrict__ keys,
                                             const float* __restrict__ points,
                                             const float* __restrict__ feats) {
    uint* smu  = (uint*)smraw;
    uint* d2u  = smu;
    uint* hist = smu + 4096;
    unsigned short* cand = (unsigned short*)(smu + 6144);

    __shared__ int  sel[KNBR];
    __shared__ uint ws[9];
    __shared__ int  sP1, sM1, sP2, sM2;
    __shared__ ull  wmin[8];

    int bk = blockIdx.x, b = bk >> 11, k = bk & 2047, tid = threadIdx.x;

    float kx = keys[(b * KK + k) * 3 + 0];
    float ky = keys[(b * KK + k) * 3 + 1];
    float kz = keys[(b * KK + k) * 3 + 2];
    const float* pb = points + (size_t)b * NN * 3;

    #pragma unroll
    for (int j = 0; j < 8; j++) hist[tid + j * 256] = 0;
    __syncthreads();

    #pragma unroll
    for (int j = 0; j < 16; j++) {
        int p = tid + j * 256;
        float dx = pb[p * 3 + 0] - kx;
        float dy = pb[p * 3 + 1] - ky;
        float dz = pb[p * 3 + 2] - kz;
        uint u = __float_as_uint(dx * dx + dy * dy + dz * dz);
        d2u[p] = u;
        atomicAdd(&hist[u >> 21], 1u);
    }
    __syncthreads();

    {
        uint cnt8[8], s = 0;
        #pragma unroll
        for (int j = 0; j < 8; j++) { cnt8[j] = hist[tid * 8 + j]; s += cnt8[j]; }
        uint e = blk_scan_excl(s, ws, 0);
        if (e < KNBR && e + s >= KNBR) {
            uint cum = e;
            #pragma unroll
            for (int j = 0; j < 8; j++) {
                if (cum + cnt8[j] >= KNBR) { sP1 = tid * 8 + j; sM1 = (int)cum; break; }
                cum += cnt8[j];
            }
        }
    }
    __syncthreads();
    int P1 = sP1, m1 = sM1;

    hist[tid] = 0;
    __syncthreads();
    #pragma unroll
    for (int j = 0; j < 16; j++) {
        int p = tid + j * 256;
        uint u = d2u[p];
        if ((int)(u >> 21) == P1) atomicAdd(&hist[(u >> 13) & 255], 1u);
    }
    __syncthreads();
    {
        uint v = hist[tid];
        uint e = blk_scan_excl(v, ws, 0);
        int need1 = KNBR - m1;
        if ((int)e < need1 && (int)(e + v) >= need1) { sP2 = tid; sM2 = (int)e; }
    }
    __syncthreads();
    int P2 = sP2, m2 = sM2;

    uint tot = 0;
    {
        uint fb = 0, fe = 0;
        #pragma unroll
        for (int j = 0; j < 16; j++) {
            int p = tid + j * 256;
            uint u = d2u[p];
            int b1 = (int)(u >> 21);
            if (b1 < P1) fb |= (1u << j);
            else if (b1 == P1) {
                int b2 = (int)((u >> 13) & 255);
                if (b2 < P2) fb |= (1u << j);
                else if (b2 == P2) fe |= (1u << j);
            }
        }
        uint packed = ((uint)__popc(fb) << 16) | (uint)__popc(fe);
        uint e = blk_scan_excl(packed, ws, &tot);
        int bB = (int)(e >> 16), bE = (int)(e & 0xFFFF);
        #pragma unroll
        for (int j = 0; j < 16; j++) {
            int p = tid + j * 256;
            if (fb & (1u << j)) sel[bB++] = p;
            if (fe & (1u << j)) cand[bE++] = (unsigned short)p;
        }
    }
    __syncthreads();

    {
        int m = m1 + m2, need = KNBR - m, cc = (int)(tot & 0xFFFF);
        for (int r = 0; r < need; r++) {
            ull best = ~0ull;
            for (int i = tid; i < cc; i += 256) {
                int p = cand[i];
                ull key = ((ull)d2u[p] << 32) | (uint)p;
                if (key < best) best = key;
            }
            #pragma unroll
            for (int off = 16; off; off >>= 1) {
                ull o = __shfl_down_sync(0xffffffffu, best, off);
                if (o < best) best = o;
            }
            if ((tid & 31) == 0) wmin[tid >> 5] = best;
            __syncthreads();
            if (tid == 0) {
                ull bb = wmin[0];
                #pragma unroll
                for (int w = 1; w < 8; w++) if (wmin[w] < bb) bb = wmin[w];
                int p = (int)(bb & 0xFFFFFFFFull);
                sel[m + r] = p;
                d2u[p] = 0xFFFFFFFFu;
            }
            __syncthreads();
        }
    }

    float* cs = (float*)smu;
    const float* fb2 = feats + (size_t)b * NN * CIN;
    __syncthreads();
    #pragma unroll
    for (int j = 0; j < 8; j++) {
        int e = tid + j * 256;
        int n = e >> 6, c = e & 63;
        int p = sel[n];
        float v;
        if (c < 3) {
            float kc = (c == 0) ? kx : ((c == 1) ? ky : kz);
            v = pb[p * 3 + c] - kc;
        } else v = fb2[p * CIN + (c - 3)];
        cs[e] = v;
    }
    __syncthreads();

    if (tid < 64) {
        float s = 0.f, ss = 0.f;
        #pragma unroll
        for (int n = 0; n < KNBR; n++) { float v = cs[n * 64 + tid]; s += v; ss += v * v; }
        g_part[(size_t)tid * NBK + bk]        = s;
        g_part[(size_t)(64 + tid) * NBK + bk] = ss;
    }
    if (tid < 32) g_selg[(size_t)bk * 32 + tid] = b * NN + sel[tid];
    if (tid < 96) g_rel[(size_t)bk * 96 + tid] = cs[(tid / 3) * 64 + (tid % 3)];
}

// ---------------------------------------------------------------------------
__global__ void __launch_bounds__(256) k_stats(const float* __restrict__ gamma,
                                               const float* __restrict__ beta) {
    int c = blockIdx.x, t = threadIdx.x;
    double s = 0.0, ss = 0.0;
    const float* ps  = g_part + (size_t)c * NBK;
    const float* pss = g_part + (size_t)(64 + c) * NBK;
    for (int i = t; i < NBK; i += 256) { s += (double)ps[i]; ss += (double)pss[i]; }
    __shared__ double rs[256], rss[256];
    rs[t] = s; rss[t] = ss;
    __syncthreads();
    for (int o = 128; o; o >>= 1) {
        if (t < o) { rs[t] += rs[t + o]; rss[t] += rss[t + o]; }
        __syncthreads();
    }
    if (t == 0) {
        double mean = rs[0] / CNTF;
        double var  = rss[0] / CNTF - mean * mean;
        float sc = (float)((1.0 / sqrt(var + 1e-5)) * (double)gamma[c]);
        g_sc[c] = sc;
        g_tc[c] = beta[c] - (float)mean * sc;
    }
}

__global__ void k_const(const float* __restrict__ sxw1, const float* __restrict__ sxb1) {
    int t = threadIdx.x;
    if (t < 64) {
        float s = sxb1[t];
        #pragma unroll 8
        for (int c = 0; c < 64; c++) s += g_tc[c] * sxw1[c * 64 + t];
        g_C1[t] = s;
    }
    if (t < 4) {
        float s = g_A[512 + t];
        #pragma unroll 8
        for (int c = 0; c < 64; c++) s += g_tc[c] * g_A[c * 4 + t];
        g_Ce[t] = s;
    }
    if (t >= 64) {
        int i = t - 64, c = i >> 6, o = i & 63;
        g_Wr1s[i] = g_sc[c] * sxw1[c * 64 + o];
    }
    if (t < 12) g_A1s[t] = g_sc[t >> 2] * g_A[(t >> 2) * 4 + (t & 3)];
}

__global__ void __launch_bounds__(64) k_pre_s1e(const float* __restrict__ feats,
                                                const float* __restrict__ sxw1) {
    int row = blockIdx.x, t = threadIdx.x;
    __shared__ float sf[61];
    if (t < 61) sf[t] = feats[(size_t)row * 61 + t] * g_sc[3 + t];
    __syncthreads();
    float acc = 0.f;
    #pragma unroll
    for (int c = 0; c < 61; c++) acc += sf[c] * sxw1[(3 + c) * 64 + t];
    g_s1pre[(size_t)row * 64 + t] = acc;
    if (t < 4) {
        float s = 0.f;
        #pragma unroll
        for (int c = 0; c < 61; c++) s += sf[c] * g_A[(3 + c) * 4 + t];
        g_epre[(size_t)row * 4 + t] = s;
    }
}

// ---------------------------------------------------------------------------
// k_main: 4 queries/CTA (M=128), 8 warps, warp w owns rows 16w..16w+15.
// GEMMs via mma.sync bf16 hi/lo (3-pass compensated).
// ---------------------------------------------------------------------------
__global__ void __launch_bounds__(256, 1) k_main(
    const float* __restrict__ nxw1, const float* __restrict__ nxb1,
    const float* __restrict__ nxb2, const float* __restrict__ nxb3,
    const float* __restrict__ sxb2, const float* __restrict__ sxb3,
    float* __restrict__ out)
{
    char* XH  = smraw + O_XH;
    char* XL  = smraw + O_XL;
    char* W2H = smraw + O_W2H;
    char* W2L = smraw + O_W2L;
    char* W3H = smraw + O_W3H;
    char* W3L = smraw + O_W3L;
    char* S2H = smraw + O_S2H;
    char* S2L = smraw + O_S2L;
    char* S3H = smraw + O_S3H;
    char* S3L = smraw + O_S3L;
    float* LAT = (float*)(smraw + O_LAT);
    float* S3F = (float*)(smraw + O_S3F);

    __shared__ int   sel_s[128];
    __shared__ float rel_s[384];
    __shared__ float setf[256];
    __shared__ float gh[16];
    __shared__ float ebuf[512];
    __shared__ float wbuf[512];

    int t = threadIdx.x, w = t >> 5, l = t & 31;
    int gid = l >> 2, tig = l & 3;
    int m0 = w * 16;
    int bk0 = blockIdx.x * 4;

    if (t < 128) sel_s[t] = g_selg[(size_t)bk0 * 32 + t];
    for (int i = t; i < 384; i += 256) rel_s[i] = g_rel[(size_t)bk0 * 96 + i];

    // stage weights into smem
    for (int i = t; i < 2176; i += 256) {
        ((uint4*)W2H)[i] = ((const uint4*)g_W2h)[i];
        ((uint4*)W2L)[i] = ((const uint4*)g_W2l)[i];
    }
    for (int i = t; i < 1088; i += 256) {
        ((uint4*)W3H)[i] = ((const uint4*)g_W3h)[i];
        ((uint4*)W3L)[i] = ((const uint4*)g_W3l)[i];
    }
    for (int i = t; i < 576; i += 256) {
        ((uint4*)S2H)[i] = ((const uint4*)g_S2h)[i];
        ((uint4*)S2L)[i] = ((const uint4*)g_S2l)[i];
        ((uint4*)S3H)[i] = ((const uint4*)g_S3h)[i];
        ((uint4*)S3L)[i] = ((const uint4*)g_S3l)[i];
    }
    __syncthreads();

    // Stage A: fill X = h1 (warp's 16 rows x 128 cols), hi/lo split
    #pragma unroll 4
    for (int i = 0; i < 32; i++) {
        int e = i * 32 + l;           // 0..1023 pairs
        int r = e >> 6, c2 = (e & 63) * 2;
        int m = m0 + r;
        int q = m >> 5, nn = m & 31;
        float rx = rel_s[q * 96 + nn * 3], ry = rel_s[q * 96 + nn * 3 + 1], rz = rel_s[q * 96 + nn * 3 + 2];
        float2 hp = *(const float2*)(g_h1pre + (size_t)sel_s[m] * 128 + c2);
        float2 b1 = *(const float2*)(nxb1 + c2);
        float2 w0 = *(const float2*)(nxw1 + c2);
        float2 w1 = *(const float2*)(nxw1 + 128 + c2);
        float2 w2 = *(const float2*)(nxw1 + 256 + c2);
        float v0 = fmaxf(hp.x + b1.x + rx * w0.x + ry * w1.x + rz * w2.x, 0.f);
        float v1 = fmaxf(hp.y + b1.y + rx * w0.y + ry * w1.y + rz * w2.y, 0.f);
        split_store(v0, v1, XH + (m * XP + c2) * 2, XL + (m * XP + c2) * 2);
    }
    __syncwarp();

    // Stage B: h2[128] = h1[128x128] @ W2
    {
        float acc[16][4];
        #pragma unroll
        for (int nt = 0; nt < 16; nt++)
            #pragma unroll
            for (int j = 0; j < 4; j++) acc[nt][j] = 0.f;
        run_mma<8, 16, 136>(XH, XL, W2H, W2L, acc, m0, gid, tig);
        __syncthreads();   // all warps done reading W2 before LAT/S3F overlays
        #pragma unroll
        for (int nt = 0; nt < 16; nt++) {
            int cb = nt * 8 + 2 * tig;
            float2 bb = *(const float2*)(nxb2 + cb);
            int r0 = m0 + gid, r1 = r0 + 8;
            split_store(fmaxf(acc[nt][0] + bb.x, 0.f), fmaxf(acc[nt][1] + bb.y, 0.f),
                        XH + (r0 * XP + cb) * 2, XL + (r0 * XP + cb) * 2);
            split_store(fmaxf(acc[nt][2] + bb.x, 0.f), fmaxf(acc[nt][3] + bb.y, 0.f),
                        XH + (r1 * XP + cb) * 2, XL + (r1 * XP + cb) * 2);
        }
    }
    __syncwarp();

    // Stage C: lat[64] = h2 @ W3 -> LAT (fp32)
    {
        float acc[8][4];
        #pragma unroll
        for (int nt = 0; nt < 8; nt++)
            #pragma unroll
            for (int j = 0; j < 4; j++) acc[nt][j] = 0.f;
        run_mma<8, 8, 136>(XH, XL, W3H, W3L, acc, m0, gid, tig);
        #pragma unroll
        for (int nt = 0; nt < 8; nt++) {
            int cb = nt * 8 + 2 * tig;
            float2 bb = *(const float2*)(nxb3 + cb);
            int r0 = m0 + gid, r1 = r0 + 8;
            *(float2*)(LAT + r0 * LP + cb) = make_float2(acc[nt][0] + bb.x, acc[nt][1] + bb.y);
            *(float2*)(LAT + r1 * LP + cb) = make_float2(acc[nt][2] + bb.x, acc[nt][3] + bb.y);
        }
    }
    __syncwarp();

    // Stage D: fill X = s1 (warp's 16 rows x 64 cols)
    #pragma unroll 4
    for (int i = 0; i < 16; i++) {
        int e = i * 32 + l;           // 0..511 pairs
        int r = e >> 5, c2 = (e & 31) * 2;
        int m = m0 + r;
        int q = m >> 5, nn = m & 31;
        float rx = rel_s[q * 96 + nn * 3], ry = rel_s[q * 96 + nn * 3 + 1], rz = rel_s[q * 96 + nn * 3 + 2];
        float2 sp = *(const float2*)(g_s1pre + (size_t)sel_s[m] * 64 + c2);
        float2 c1 = *(const float2*)(g_C1 + c2);
        float2 w0 = *(const float2*)(g_Wr1s + c2);
        float2 w1 = *(const float2*)(g_Wr1s + 64 + c2);
        float2 w2 = *(const float2*)(g_Wr1s + 128 + c2);
        float v0 = fmaxf(sp.x + c1.x + rx * w0.x + ry * w1.x + rz * w2.x, 0.f);
        float v1 = fmaxf(sp.y + c1.y + rx * w0.y + ry * w1.y + rz * w2.y, 0.f);
        split_store(v0, v1, XH + (m * XP + c2) * 2, XL + (m * XP + c2) * 2);
    }
    __syncwarp();

    // Stage E: s2 = s1 @ S2
    {
        float acc[8][4];
        #pragma unroll
        for (int nt = 0; nt < 8; nt++)
            #pragma unroll
            for (int j = 0; j < 4; j++) acc[nt][j] = 0.f;
        run_mma<4, 8, 72>(XH, XL, S2H, S2L, acc, m0, gid, tig);
        #pragma unroll
        for (int nt = 0; nt < 8; nt++) {
            int cb = nt * 8 + 2 * tig;
            float2 bb = *(const float2*)(sxb2 + cb);
            int r0 = m0 + gid, r1 = r0 + 8;
            split_store(fmaxf(acc[nt][0] + bb.x, 0.f), fmaxf(acc[nt][1] + bb.y, 0.f),
                        XH + (r0 * XP + cb) * 2, XL + (r0 * XP + cb) * 2);
            split_store(fmaxf(acc[nt][2] + bb.x, 0.f), fmaxf(acc[nt][3] + bb.y, 0.f),
                        XH + (r1 * XP + cb) * 2, XL + (r1 * XP + cb) * 2);
        }
    }
    __syncwarp();

    // Stage F: s3 = s2 @ S3 -> S3F (fp32)
    {
        float acc[8][4];
        #pragma unroll
        for (int nt = 0; nt < 8; nt++)
            #pragma unroll
            for (int j = 0; j < 4; j++) acc[nt][j] = 0.f;
        run_mma<4, 8, 72>(XH, XL, S3H, S3L, acc, m0, gid, tig);
        #pragma unroll
        for (int nt = 0; nt < 8; nt++) {
            int cb = nt * 8 + 2 * tig;
            float2 bb = *(const float2*)(sxb3 + cb);
            int r0 = m0 + gid, r1 = r0 + 8;
            *(float2*)(S3F + r0 * LP + cb) = make_float2(acc[nt][0] + bb.x, acc[nt][1] + bb.y);
            *(float2*)(S3F + r1 * LP + cb) = make_float2(acc[nt][2] + bb.x, acc[nt][3] + bb.y);
        }
    }
    __syncthreads();

    // setf[q][c] = sum_n s3[q*32+n][c]
    {
        int q = t >> 6, c = t & 63;
        float s = 0.f;
        #pragma unroll
        for (int n = 0; n < 32; n++) s += S3F[(q * 32 + n) * LP + c];
        setf[t] = s;
    }
    __syncthreads();
    if (t < 16) {
        int q = t >> 2, h = t & 3;
        float s = g_Ce[h];
        #pragma unroll 8
        for (int c = 0; c < 64; c++) s += setf[q * 64 + c] * g_A[(64 + c) * 4 + h];
        gh[t] = s;
    }
    __syncthreads();
    #pragma unroll
    for (int r = 0; r < 2; r++) {
        int idx = t + r * 256;
        int q = idx >> 7, i2 = idx & 127, n = i2 >> 2, h = i2 & 3;
        int gn = q * 32 + n;
        ebuf[idx] = gh[q * 4 + h] + g_epre[(size_t)sel_s[gn] * 4 + h]
                  + rel_s[q * 96 + n * 3]     * g_A1s[h]
                  + rel_s[q * 96 + n * 3 + 1] * g_A1s[4 + h]
                  + rel_s[q * 96 + n * 3 + 2] * g_A1s[8 + h];
    }
    __syncthreads();
    if (t < 16) {
        int q = t >> 2, h = t & 3;
        float mx = -INFINITY;
        #pragma unroll
        for (int n = 0; n < 32; n++) mx = fmaxf(mx, ebuf[q * 128 + n * 4 + h]);
        float s = 0.f;
        #pragma unroll
        for (int n = 0; n < 32; n++) {
            float ex = expf(ebuf[q * 128 + n * 4 + h] - mx);
            wbuf[q * 128 + n * 4 + h] = ex;
            s += ex;
        }
        float inv = 1.f / s;
        #pragma unroll
        for (int n = 0; n < 32; n++) wbuf[q * 128 + n * 4 + h] *= inv;
    }
    __syncthreads();
    #pragma unroll
    for (int r = 0; r < 4; r++) {
        int idx = t + r * 256;
        int q = idx >> 8, i2 = idx & 255, o = i2 >> 2, h = i2 & 3;
        float s = 0.f;
        #pragma unroll
        for (int n = 0; n < 32; n++)
            s += LAT[(q * 32 + n) * LP + o] * wbuf[q * 128 + n * 4 + h];
        out[(size_t)(bk0 + q) * 256 + i2] = s;
    }
}

// ---------------------------------------------------------------------------
extern "C" void kernel_launch(void* const* d_in, const int* in_sizes, int n_in,
                              void* d_out, int out_size) {
    (void)in_sizes; (void)n_in; (void)out_size;
    const float* keys  = (const float*)d_in[0];
    const float* points= (const float*)d_in[1];
    const float* feats = (const float*)d_in[2];
    const float* nxw1  = (const float*)d_in[3];
    const float* nxb1  = (const float*)d_in[4];
    const float* nxw2  = (const float*)d_in[5];
    const float* nxb2  = (const float*)d_in[6];
    const float* nxw3  = (const float*)d_in[7];
    const float* nxb3  = (const float*)d_in[8];
    const float* sxw1  = (const float*)d_in[9];
    const float* sxb1  = (const float*)d_in[10];
    const float* sxw2  = (const float*)d_in[11];
    const float* sxb2  = (const float*)d_in[12];
    const float* sxw3  = (const float*)d_in[13];
    const float* sxb3  = (const float*)d_in[14];
    const float* attw  = (const float*)d_in[15];
    const float* attb  = (const float*)d_in[16];
    const float* attq  = (const float*)d_in[17];
    const float* gamma = (const float*)d_in[18];
    const float* beta  = (const float*)d_in[19];
    float* out = (float*)d_out;

    cudaFuncSetAttribute(k_main, cudaFuncAttributeMaxDynamicSharedMemorySize, SM_TOTAL);

    k_prep<<<2, 256>>>(attw, attb, attq);
    k_packw<<<128, 256>>>(nxw2, nxw3, sxw2, sxw3);
    k_pre_h1<<<NPTS, 128>>>(feats, nxw1);
    k_knn<<<NBK, 256, 32768>>>(keys, points, feats);
    k_stats<<<64, 256>>>(gamma, beta);
    k_const<<<1, 256>>>(sxw1, sxb1);
    k_pre_s1e<<<NPTS, 64>>>(feats, sxw1);
    k_main<<<NBK / 4, 256, SM_TOTAL>>>(nxw1, nxb1, nxb2, nxb3, sxb2, sxb3, out);
}